// round 4
// baseline (speedup 1.0000x reference)
#include <cuda_runtime.h>
#include <cuda_bf16.h>
#include <math.h>

#define NN     46080
#define EE     737280
#define BG     512
#define NODES  90
#define EPG    1440
#define FIN    90
#define HH     128
#define HL     64
#define XCW    (3*HH)    // 384
#define LDA1   (NODES*XCW)  // 34560

// ---------------- device scratch ----------------
__device__ float g_dis[NN];
__device__ int   g_off[NN];      // global CSR offsets
__device__ int   g_cnt[NN];
__device__ int   g_csrc[EE];     // LOCAL source index (0..89)
__device__ float g_cnorm[EE];
__device__ float g_agg[NN*HH];   // aggregated features (lda = F)
__device__ float g_xc[NN*XCW];   // [h1|h2|h3]; viewed as z [512, 34560]
__device__ float g_acc[BG*HL];   // lin1 split-K accumulator

// ---------------- tf32 helpers ----------------
__device__ __forceinline__ unsigned f2tf(float f) {
    unsigned r; asm("cvt.rna.tf32.f32 %0, %1;" : "=r"(r) : "f"(f)); return r;
}
__device__ __forceinline__ void mma8(float* c, const unsigned* a, const unsigned* b) {
    asm volatile("mma.sync.aligned.m16n8k8.row.col.f32.tf32.tf32.f32 "
        "{%0,%1,%2,%3}, {%4,%5,%6,%7}, {%8,%9}, {%0,%1,%2,%3};"
        : "+f"(c[0]), "+f"(c[1]), "+f"(c[2]), "+f"(c[3])
        : "r"(a[0]), "r"(a[1]), "r"(a[2]), "r"(a[3]), "r"(b[0]), "r"(b[1]));
}

// ================= prologue: per-graph CSR build + dis + layer-1 aggregation =================
__global__ void k_prep(const float* __restrict__ x, const float* __restrict__ eattr,
                       const int* __restrict__ ei) {
    __shared__ float sdeg[NODES];
    __shared__ float sdis[NODES];
    __shared__ int   scnt[NODES];
    __shared__ int   soff[NODES];
    __shared__ int   scur[NODES];
    __shared__ short ssrc[EPG];
    __shared__ float snorm[EPG];
    __shared__ float sx[NODES*FIN];   // 32.4 KB

    const int g = blockIdx.x;
    const int t = threadIdx.x;
    const int ebase = g*EPG;

    if (t < NODES) { sdeg[t] = 1.0f; scnt[t] = 0; scur[t] = 0; }
    if (t < HL) g_acc[g*HL + t] = 0.0f;
    __syncthreads();

    for (int e = t; e < EPG; e += blockDim.x) {
        int d = ei[EE + ebase + e] - g*NODES;
        atomicAdd(&sdeg[d], eattr[ebase + e]);
        atomicAdd(&scnt[d], 1);
    }
    __syncthreads();
    if (t < NODES) sdis[t] = rsqrtf(sdeg[t]);
    __syncthreads();
    if (t == 0) {
        int acc = 0;
        #pragma unroll 1
        for (int n = 0; n < NODES; n++) { soff[n] = acc; acc += scnt[n]; }
    }
    __syncthreads();
    for (int e = t; e < EPG; e += blockDim.x) {
        int s = ei[ebase + e] - g*NODES;
        int d = ei[EE + ebase + e] - g*NODES;
        int p = soff[d] + atomicAdd(&scur[d], 1);
        float nm = sdis[s] * eattr[ebase + e] * sdis[d];
        ssrc[p] = (short)s;  snorm[p] = nm;
        g_csrc[ebase + p] = s;  g_cnorm[ebase + p] = nm;
    }
    if (t < NODES) {
        g_dis[g*NODES + t] = sdis[t];
        g_off[g*NODES + t] = ebase + soff[t];
        g_cnt[g*NODES + t] = scnt[t];
    }
    // load x tile for this graph
    const float* gx = x + (long)g*NODES*FIN;
    for (int i = t; i < NODES*FIN; i += blockDim.x) sx[i] = gx[i];
    __syncthreads();

    // layer-1 aggregation: one warp per node
    int warp = t >> 5, lane = t & 31;
    for (int node = warp; node < NODES; node += (blockDim.x >> 5)) {
        float selfnm = sdis[node]*sdis[node];
        float acc[3];
        #pragma unroll
        for (int j = 0; j < 3; j++) {
            int f = lane + 32*j;
            acc[j] = (f < FIN) ? selfnm * sx[node*FIN + f] : 0.0f;
        }
        int o = soff[node], c = scnt[node];
        for (int p = o; p < o + c; p++) {
            int sl = ssrc[p];
            float nm = snorm[p];
            #pragma unroll
            for (int j = 0; j < 3; j++) {
                int f = lane + 32*j;
                if (f < FIN) acc[j] = fmaf(nm, sx[sl*FIN + f], acc[j]);
            }
        }
        #pragma unroll
        for (int j = 0; j < 3; j++) {
            int f = lane + 32*j;
            if (f < FIN) g_agg[(g*NODES + node)*FIN + f] = acc[j];
        }
    }
}

// ================= aggregation for layers 2/3 (from g_xc col colOff) =================
__global__ void k_aggregate(int colOff) {
    __shared__ float sh[NODES*HH];   // 46 KB — OK static (<48KB)
    int g = blockIdx.x;
    const float* gin = g_xc + (long)g * NODES * XCW + colOff;
    for (int idx = threadIdx.x; idx < NODES*HH; idx += blockDim.x) {
        int r = idx >> 7, c = idx & 127;
        sh[idx] = gin[r*XCW + c];
    }
    __syncthreads();

    int warp = threadIdx.x >> 5, lane = threadIdx.x & 31;
    for (int node = warp; node < NODES; node += (blockDim.x >> 5)) {
        int gi = g*NODES + node;
        float ds = g_dis[gi];
        float selfnm = ds*ds;
        float acc[4];
        #pragma unroll
        for (int j = 0; j < 4; j++) acc[j] = selfnm * sh[node*HH + lane + 32*j];
        int o = g_off[gi], c = g_cnt[gi];
        for (int p = o; p < o + c; p++) {
            int sl = g_csrc[p];
            float nm = g_cnorm[p];
            #pragma unroll
            for (int j = 0; j < 4; j++)
                acc[j] = fmaf(nm, sh[sl*HH + lane + 32*j], acc[j]);
        }
        #pragma unroll
        for (int j = 0; j < 4; j++) g_agg[gi*HH + lane + 32*j] = acc[j];
    }
}

// ================= conv GEMM (tf32 split): xc[:,colOff:+128] = relu(agg@W + b) =================
// CTA: 256 thr (8 warps, 4x2), tile M=128 N=128, KB=16. Warp tile 32x64.
template<int K>
__global__ void __launch_bounds__(256, 2) k_gemm_conv(const float* __restrict__ W,
                                                      const float* __restrict__ bias,
                                                      int colOff) {
    __shared__ unsigned Ah[16][132], Al[16][132];
    __shared__ unsigned Bh[16][132], Bl[16][132];
    const int t = threadIdx.x, lane = t & 31, wid = t >> 5;
    const int wm = wid >> 1, wn = wid & 1;
    const int gid = lane >> 2, tig = lane & 3;
    const int row0 = blockIdx.x * 128;

    float acc[2][8][4];
    #pragma unroll
    for (int i = 0; i < 2; i++)
        #pragma unroll
        for (int j = 0; j < 8; j++)
            #pragma unroll
            for (int q = 0; q < 4; q++) acc[i][j][q] = 0.0f;

    const int KT = (K + 15) / 16;
    for (int kt = 0; kt < KT; kt++) {
        int k0 = kt * 16;
        #pragma unroll
        for (int j = 0; j < 8; j++) {          // A: 16x128
            int idx = t*8 + j; int m = idx >> 4, k = idx & 15;
            float v = (k0 + k < K) ? g_agg[(long)(row0 + m)*K + k0 + k] : 0.0f;
            unsigned h = f2tf(v);
            Ah[k][m] = h; Al[k][m] = f2tf(v - __uint_as_float(h));
        }
        #pragma unroll
        for (int j = 0; j < 8; j++) {          // B: 16x128
            int idx = t*8 + j; int n = idx & 127, k = idx >> 7;
            float v = (k0 + k < K) ? W[(k0 + k)*HH + n] : 0.0f;
            unsigned h = f2tf(v);
            Bh[k][n] = h; Bl[k][n] = f2tf(v - __uint_as_float(h));
        }
        __syncthreads();
        #pragma unroll
        for (int kk = 0; kk < 16; kk += 8) {
            unsigned a_h[2][4], a_l[2][4];
            #pragma unroll
            for (int i = 0; i < 2; i++) {
                int m = wm*32 + i*16;
                a_h[i][0] = Ah[kk+tig  ][m+gid];   a_h[i][1] = Ah[kk+tig  ][m+gid+8];
                a_h[i][2] = Ah[kk+tig+4][m+gid];   a_h[i][3] = Ah[kk+tig+4][m+gid+8];
                a_l[i][0] = Al[kk+tig  ][m+gid];   a_l[i][1] = Al[kk+tig  ][m+gid+8];
                a_l[i][2] = Al[kk+tig+4][m+gid];   a_l[i][3] = Al[kk+tig+4][m+gid+8];
            }
            #pragma unroll
            for (int j = 0; j < 8; j++) {
                int n = wn*64 + j*8;
                unsigned b_h[2] = { Bh[kk+tig][n+gid], Bh[kk+tig+4][n+gid] };
                unsigned b_l[2] = { Bl[kk+tig][n+gid], Bl[kk+tig+4][n+gid] };
                #pragma unroll
                for (int i = 0; i < 2; i++) {
                    mma8(acc[i][j], a_h[i], b_h);
                    mma8(acc[i][j], a_h[i], b_l);
                    mma8(acc[i][j], a_l[i], b_h);
                }
            }
        }
        __syncthreads();
    }
    // epilogue: relu(+bias) -> g_xc
    #pragma unroll
    for (int j = 0; j < 8; j++) {
        int n = wn*64 + j*8 + 2*tig;
        float b0 = bias[n], b1 = bias[n+1];
        #pragma unroll
        for (int i = 0; i < 2; i++) {
            int r = row0 + wm*32 + i*16 + gid;
            float2 v0 = { fmaxf(acc[i][j][0] + b0, 0.0f), fmaxf(acc[i][j][1] + b1, 0.0f) };
            float2 v1 = { fmaxf(acc[i][j][2] + b0, 0.0f), fmaxf(acc[i][j][3] + b1, 0.0f) };
            *(float2*)&g_xc[(long)r*XCW + colOff + n]       = v0;
            *(float2*)&g_xc[(long)(r+8)*XCW + colOff + n]   = v1;
        }
    }
}

// ================= lin1 (tf32 split, split-K): g_acc += z @ lin1_W =================
// CTA: 256 thr (8 warps, 4x2), tile M=128 N=64, K-chunk 768. Warp tile 32x32.
__global__ void __launch_bounds__(256, 2) k_lin1(const float* __restrict__ W) {
    __shared__ unsigned Ah[16][132], Al[16][132];
    __shared__ unsigned Bh[16][68],  Bl[16][68];
    const int t = threadIdx.x, lane = t & 31, wid = t >> 5;
    const int wm = wid >> 1, wn = wid & 1;
    const int gid = lane >> 2, tig = lane & 3;
    const int row0  = blockIdx.x * 128;
    const int kbase = blockIdx.y * 768;

    float acc[2][4][4];
    #pragma unroll
    for (int i = 0; i < 2; i++)
        #pragma unroll
        for (int j = 0; j < 4; j++)
            #pragma unroll
            for (int q = 0; q < 4; q++) acc[i][j][q] = 0.0f;

    for (int kt = 0; kt < 48; kt++) {
        int k0 = kbase + kt*16;
        #pragma unroll
        for (int j = 0; j < 8; j++) {          // A: 16x128 from g_xc
            int idx = t*8 + j; int m = idx >> 4, k = idx & 15;
            float v = g_xc[(long)(row0 + m)*LDA1 + k0 + k];
            unsigned h = f2tf(v);
            Ah[k][m] = h; Al[k][m] = f2tf(v - __uint_as_float(h));
        }
        #pragma unroll
        for (int j = 0; j < 4; j++) {          // B: 16x64
            int idx = t*4 + j; int n = idx & 63, k = idx >> 6;
            float v = W[(k0 + k)*HL + n];
            unsigned h = f2tf(v);
            Bh[k][n] = h; Bl[k][n] = f2tf(v - __uint_as_float(h));
        }
        __syncthreads();
        #pragma unroll
        for (int kk = 0; kk < 16; kk += 8) {
            unsigned a_h[2][4], a_l[2][4];
            #pragma unroll
            for (int i = 0; i < 2; i++) {
                int m = wm*32 + i*16;
                a_h[i][0] = Ah[kk+tig  ][m+gid];   a_h[i][1] = Ah[kk+tig  ][m+gid+8];
                a_h[i][2] = Ah[kk+tig+4][m+gid];   a_h[i][3] = Ah[kk+tig+4][m+gid+8];
                a_l[i][0] = Al[kk+tig  ][m+gid];   a_l[i][1] = Al[kk+tig  ][m+gid+8];
                a_l[i][2] = Al[kk+tig+4][m+gid];   a_l[i][3] = Al[kk+tig+4][m+gid+8];
            }
            #pragma unroll
            for (int j = 0; j < 4; j++) {
                int n = wn*32 + j*8;
                unsigned b_h[2] = { Bh[kk+tig][n+gid], Bh[kk+tig+4][n+gid] };
                unsigned b_l[2] = { Bl[kk+tig][n+gid], Bl[kk+tig+4][n+gid] };
                #pragma unroll
                for (int i = 0; i < 2; i++) {
                    mma8(acc[i][j], a_h[i], b_h);
                    mma8(acc[i][j], a_h[i], b_l);
                    mma8(acc[i][j], a_l[i], b_h);
                }
            }
        }
        __syncthreads();
    }
    #pragma unroll
    for (int j = 0; j < 4; j++) {
        int n = wn*32 + j*8 + 2*tig;
        #pragma unroll
        for (int i = 0; i < 2; i++) {
            int r = row0 + wm*32 + i*16 + gid;
            atomicAdd(&g_acc[r*HL + n],     acc[i][j][0]);
            atomicAdd(&g_acc[r*HL + n + 1], acc[i][j][1]);
            atomicAdd(&g_acc[(r+8)*HL + n],     acc[i][j][2]);
            atomicAdd(&g_acc[(r+8)*HL + n + 1], acc[i][j][3]);
        }
    }
}

// ================= epilogue: relu -> lin2 -> log_softmax =================
__global__ void k_final(const float* __restrict__ b1, const float* __restrict__ W2,
                        const float* __restrict__ b2, float* __restrict__ out) {
    int g = blockIdx.x*blockDim.x + threadIdx.x;
    if (g >= BG) return;
    float l0 = b2[0], l1 = b2[1];
    #pragma unroll 8
    for (int j = 0; j < HL; j++) {
        float h = fmaxf(g_acc[g*HL + j] + b1[j], 0.0f);
        l0 = fmaf(h, W2[j*2 + 0], l0);
        l1 = fmaf(h, W2[j*2 + 1], l1);
    }
    float m = fmaxf(l0, l1);
    float lse = m + logf(expf(l0 - m) + expf(l1 - m));
    out[g*2 + 0] = l0 - lse;
    out[g*2 + 1] = l1 - lse;
}

// ================= launch =================
extern "C" void kernel_launch(void* const* d_in, const int* in_sizes, int n_in,
                              void* d_out, int out_size) {
    const float* x      = (const float*)d_in[0];
    const float* eattr  = (const float*)d_in[1];
    const float* W1     = (const float*)d_in[2];
    const float* b1     = (const float*)d_in[3];
    const float* W2     = (const float*)d_in[4];
    const float* b2     = (const float*)d_in[5];
    const float* W3     = (const float*)d_in[6];
    const float* b3     = (const float*)d_in[7];
    const float* lin1W  = (const float*)d_in[8];
    const float* lin1b  = (const float*)d_in[9];
    const float* lin2W  = (const float*)d_in[10];
    const float* lin2b  = (const float*)d_in[11];
    const int*   eidx   = (const int*)d_in[12];   // int32
    float*       out    = (float*)d_out;

    k_prep<<<BG, 256>>>(x, eattr, eidx);               // CSR + dis + agg1 + zero acc
    k_gemm_conv<FIN><<<NN/128, 256>>>(W1, b1, 0);      // h1 -> xc[:,0:128]
    k_aggregate<<<BG, 256>>>(0);
    k_gemm_conv<HH><<<NN/128, 256>>>(W2, b2, HH);      // h2 -> xc[:,128:256]
    k_aggregate<<<BG, 256>>>(HH);
    k_gemm_conv<HH><<<NN/128, 256>>>(W3, b3, 2*HH);    // h3 -> xc[:,256:384]
    dim3 g1(BG/128, 45);
    k_lin1<<<g1, 256>>>(lin1W);
    k_final<<<(BG + 255)/256, 256>>>(lin1b, lin2W, lin2b, out);
}

// round 5
// speedup vs baseline: 1.3097x; 1.3097x over previous
#include <cuda_runtime.h>
#include <cuda_bf16.h>
#include <math.h>

#define NN     46080
#define EE     737280
#define BG     512
#define NODES  90
#define EPG    1440
#define FIN    90
#define HH     128
#define HL     64
#define XCW    (3*HH)       // 384
#define LDA1   (NODES*XCW)  // 34560

// ---------------- device scratch ----------------
__device__ float g_dis[NN];
__device__ int   g_off[NN];
__device__ int   g_cnt[NN];
__device__ int   g_csrc[EE];     // LOCAL source index (0..89)
__device__ float g_cnorm[EE];
__device__ float g_agg[NN*HH];
__device__ float g_xc[NN*XCW];   // [h1|h2|h3]; viewed as z [512, 34560]
__device__ float g_acc[BG*HL];

// ---------------- bf16 split helpers ----------------
__device__ __forceinline__ void f2bf2(float v0, float v1, unsigned &h, unsigned &l) {
    __nv_bfloat16 h0 = __float2bfloat16(v0), h1 = __float2bfloat16(v1);
    float r0 = v0 - __bfloat162float(h0);
    float r1 = v1 - __bfloat162float(h1);
    __nv_bfloat16 l0 = __float2bfloat16(r0), l1 = __float2bfloat16(r1);
    h = ((unsigned)__bfloat16_as_ushort(h1) << 16) | (unsigned)__bfloat16_as_ushort(h0);
    l = ((unsigned)__bfloat16_as_ushort(l1) << 16) | (unsigned)__bfloat16_as_ushort(l0);
}
__device__ __forceinline__ void mma16(float* c, const unsigned* a, const unsigned* b) {
    asm volatile("mma.sync.aligned.m16n8k16.row.col.f32.bf16.bf16.f32 "
        "{%0,%1,%2,%3}, {%4,%5,%6,%7}, {%8,%9}, {%0,%1,%2,%3};"
        : "+f"(c[0]), "+f"(c[1]), "+f"(c[2]), "+f"(c[3])
        : "r"(a[0]), "r"(a[1]), "r"(a[2]), "r"(a[3]), "r"(b[0]), "r"(b[1]));
}

// ================= prologue: per-graph CSR build + dis + layer-1 aggregation =================
__global__ void k_prep(const float* __restrict__ x, const float* __restrict__ eattr,
                       const int* __restrict__ ei) {
    __shared__ float sdeg[NODES];
    __shared__ float sdis[NODES];
    __shared__ int   scnt[NODES];
    __shared__ int   soff[NODES];
    __shared__ int   scur[NODES];
    __shared__ short ssrc[EPG];
    __shared__ float snorm[EPG];
    __shared__ float sx[NODES*FIN];

    const int g = blockIdx.x;
    const int t = threadIdx.x;
    const int ebase = g*EPG;

    if (t < NODES) { sdeg[t] = 1.0f; scnt[t] = 0; scur[t] = 0; }
    if (t < HL) g_acc[g*HL + t] = 0.0f;
    __syncthreads();

    for (int e = t; e < EPG; e += blockDim.x) {
        int d = ei[EE + ebase + e] - g*NODES;
        atomicAdd(&sdeg[d], eattr[ebase + e]);
        atomicAdd(&scnt[d], 1);
    }
    __syncthreads();
    if (t < NODES) sdis[t] = rsqrtf(sdeg[t]);
    __syncthreads();
    if (t == 0) {
        int acc = 0;
        #pragma unroll 1
        for (int n = 0; n < NODES; n++) { soff[n] = acc; acc += scnt[n]; }
    }
    __syncthreads();
    for (int e = t; e < EPG; e += blockDim.x) {
        int s = ei[ebase + e] - g*NODES;
        int d = ei[EE + ebase + e] - g*NODES;
        int p = soff[d] + atomicAdd(&scur[d], 1);
        float nm = sdis[s] * eattr[ebase + e] * sdis[d];
        ssrc[p] = (short)s;  snorm[p] = nm;
        g_csrc[ebase + p] = s;  g_cnorm[ebase + p] = nm;
    }
    if (t < NODES) {
        g_dis[g*NODES + t] = sdis[t];
        g_off[g*NODES + t] = ebase + soff[t];
        g_cnt[g*NODES + t] = scnt[t];
    }
    const float* gx = x + (long)g*NODES*FIN;
    for (int i = t; i < NODES*FIN; i += blockDim.x) sx[i] = gx[i];
    __syncthreads();

    int warp = t >> 5, lane = t & 31;
    for (int node = warp; node < NODES; node += (blockDim.x >> 5)) {
        float selfnm = sdis[node]*sdis[node];
        float acc[3];
        #pragma unroll
        for (int j = 0; j < 3; j++) {
            int f = lane + 32*j;
            acc[j] = (f < FIN) ? selfnm * sx[node*FIN + f] : 0.0f;
        }
        int o = soff[node], c = scnt[node];
        for (int p = o; p < o + c; p++) {
            int sl = ssrc[p];
            float nm = snorm[p];
            #pragma unroll
            for (int j = 0; j < 3; j++) {
                int f = lane + 32*j;
                if (f < FIN) acc[j] = fmaf(nm, sx[sl*FIN + f], acc[j]);
            }
        }
        #pragma unroll
        for (int j = 0; j < 3; j++) {
            int f = lane + 32*j;
            if (f < FIN) g_agg[(g*NODES + node)*FIN + f] = acc[j];
        }
    }
}

// ================= aggregation for layers 2/3 =================
__global__ void k_aggregate(int colOff) {
    __shared__ float sh[NODES*HH];
    int g = blockIdx.x;
    const float* gin = g_xc + (long)g * NODES * XCW + colOff;
    for (int idx = threadIdx.x; idx < NODES*HH; idx += blockDim.x) {
        int r = idx >> 7, c = idx & 127;
        sh[idx] = gin[r*XCW + c];
    }
    __syncthreads();

    int warp = threadIdx.x >> 5, lane = threadIdx.x & 31;
    for (int node = warp; node < NODES; node += (blockDim.x >> 5)) {
        int gi = g*NODES + node;
        float ds = g_dis[gi];
        float selfnm = ds*ds;
        float acc[4];
        #pragma unroll
        for (int j = 0; j < 4; j++) acc[j] = selfnm * sh[node*HH + lane + 32*j];
        int o = g_off[gi], c = g_cnt[gi];
        for (int p = o; p < o + c; p++) {
            int sl = g_csrc[p];
            float nm = g_cnorm[p];
            #pragma unroll
            for (int j = 0; j < 4; j++)
                acc[j] = fmaf(nm, sh[sl*HH + lane + 32*j], acc[j]);
        }
        #pragma unroll
        for (int j = 0; j < 4; j++) g_agg[gi*HH + lane + 32*j] = acc[j];
    }
}

// ================= conv GEMM (bf16 split-3, m16n8k16) =================
// CTA: 256 thr (8 warps, 4x2), tile M=128 N=128, KB=16 (8 bf16x2 pairs).
template<int K>
__global__ void __launch_bounds__(256, 2) k_gemm_conv(const float* __restrict__ W,
                                                      const float* __restrict__ bias,
                                                      int colOff) {
    __shared__ unsigned Ah[8][132], Al[8][132];
    __shared__ unsigned Bh[8][132], Bl[8][132];
    const int t = threadIdx.x, lane = t & 31, wid = t >> 5;
    const int wm = wid >> 1, wn = wid & 1;
    const int gid = lane >> 2, tig = lane & 3;
    const int row0 = blockIdx.x * 128;

    float acc[2][8][4];
    #pragma unroll
    for (int i = 0; i < 2; i++)
        #pragma unroll
        for (int j = 0; j < 8; j++)
            #pragma unroll
            for (int q = 0; q < 4; q++) acc[i][j][q] = 0.0f;

    const int KT = (K + 15) / 16;
    for (int kt = 0; kt < KT; kt++) {
        int k0 = kt * 16;
        #pragma unroll
        for (int j = 0; j < 4; j++) {   // A: 128 m x 8 pairs = 1024 pairs
            int idx = t*4 + j; int m = idx >> 3, k2 = idx & 7;
            int ka = k0 + 2*k2;
            float v0 = (K % 16 == 0 || ka     < K) ? g_agg[(long)(row0 + m)*K + ka]     : 0.0f;
            float v1 = (K % 16 == 0 || ka + 1 < K) ? g_agg[(long)(row0 + m)*K + ka + 1] : 0.0f;
            unsigned h, l; f2bf2(v0, v1, h, l);
            Ah[k2][m] = h; Al[k2][m] = l;
        }
        #pragma unroll
        for (int j = 0; j < 4; j++) {   // B: 8 pairs x 128 n
            int idx = t*4 + j; int k2 = idx >> 7, n = idx & 127;
            int ka = k0 + 2*k2;
            float v0 = (K % 16 == 0 || ka     < K) ? W[ka*HH + n]       : 0.0f;
            float v1 = (K % 16 == 0 || ka + 1 < K) ? W[(ka + 1)*HH + n] : 0.0f;
            unsigned h, l; f2bf2(v0, v1, h, l);
            Bh[k2][n] = h; Bl[k2][n] = l;
        }
        __syncthreads();
        unsigned a_h[2][4], a_l[2][4];
        #pragma unroll
        for (int i = 0; i < 2; i++) {
            int m = wm*32 + i*16;
            a_h[i][0] = Ah[tig  ][m+gid]; a_h[i][1] = Ah[tig  ][m+gid+8];
            a_h[i][2] = Ah[tig+4][m+gid]; a_h[i][3] = Ah[tig+4][m+gid+8];
            a_l[i][0] = Al[tig  ][m+gid]; a_l[i][1] = Al[tig  ][m+gid+8];
            a_l[i][2] = Al[tig+4][m+gid]; a_l[i][3] = Al[tig+4][m+gid+8];
        }
        #pragma unroll
        for (int j = 0; j < 8; j++) {
            int n = wn*64 + j*8;
            unsigned b_h[2] = { Bh[tig][n+gid], Bh[tig+4][n+gid] };
            unsigned b_l[2] = { Bl[tig][n+gid], Bl[tig+4][n+gid] };
            #pragma unroll
            for (int i = 0; i < 2; i++) {
                mma16(acc[i][j], a_h[i], b_h);
                mma16(acc[i][j], a_h[i], b_l);
                mma16(acc[i][j], a_l[i], b_h);
            }
        }
        __syncthreads();
    }
    #pragma unroll
    for (int j = 0; j < 8; j++) {
        int n = wn*64 + j*8 + 2*tig;
        float b0 = bias[n], b1 = bias[n+1];
        #pragma unroll
        for (int i = 0; i < 2; i++) {
            int r = row0 + wm*32 + i*16 + gid;
            float2 v0 = { fmaxf(acc[i][j][0] + b0, 0.0f), fmaxf(acc[i][j][1] + b1, 0.0f) };
            float2 v1 = { fmaxf(acc[i][j][2] + b0, 0.0f), fmaxf(acc[i][j][3] + b1, 0.0f) };
            *(float2*)&g_xc[(long)r*XCW + colOff + n]     = v0;
            *(float2*)&g_xc[(long)(r+8)*XCW + colOff + n] = v1;
        }
    }
}

// ================= lin1 (bf16 split-3, split-K) =================
// CTA: 256 thr (8 warps, 4x2), tile M=128 N=64, K-chunk 768 (48 k-tiles).
__global__ void __launch_bounds__(256, 2) k_lin1(const float* __restrict__ W) {
    __shared__ unsigned Ah[8][132], Al[8][132];
    __shared__ unsigned Bh[8][68],  Bl[8][68];
    const int t = threadIdx.x, lane = t & 31, wid = t >> 5;
    const int wm = wid >> 1, wn = wid & 1;
    const int gid = lane >> 2, tig = lane & 3;
    const int row0  = blockIdx.x * 128;
    const int kbase = blockIdx.y * 768;

    float acc[2][4][4];
    #pragma unroll
    for (int i = 0; i < 2; i++)
        #pragma unroll
        for (int j = 0; j < 4; j++)
            #pragma unroll
            for (int q = 0; q < 4; q++) acc[i][j][q] = 0.0f;

    for (int kt = 0; kt < 48; kt++) {
        int k0 = kbase + kt*16;
        #pragma unroll
        for (int j = 0; j < 4; j++) {   // A: 128 m x 8 pairs
            int idx = t*4 + j; int m = idx >> 3, k2 = idx & 7;
            const float* p = &g_xc[(long)(row0 + m)*LDA1 + k0 + 2*k2];
            unsigned h, l; f2bf2(p[0], p[1], h, l);
            Ah[k2][m] = h; Al[k2][m] = l;
        }
        #pragma unroll
        for (int j = 0; j < 2; j++) {   // B: 8 pairs x 64 n
            int idx = t*2 + j; int k2 = idx >> 6, n = idx & 63;
            int ka = k0 + 2*k2;
            unsigned h, l; f2bf2(W[ka*HL + n], W[(ka+1)*HL + n], h, l);
            Bh[k2][n] = h; Bl[k2][n] = l;
        }
        __syncthreads();
        unsigned a_h[2][4], a_l[2][4];
        #pragma unroll
        for (int i = 0; i < 2; i++) {
            int m = wm*32 + i*16;
            a_h[i][0] = Ah[tig  ][m+gid]; a_h[i][1] = Ah[tig  ][m+gid+8];
            a_h[i][2] = Ah[tig+4][m+gid]; a_h[i][3] = Ah[tig+4][m+gid+8];
            a_l[i][0] = Al[tig  ][m+gid]; a_l[i][1] = Al[tig  ][m+gid+8];
            a_l[i][2] = Al[tig+4][m+gid]; a_l[i][3] = Al[tig+4][m+gid+8];
        }
        #pragma unroll
        for (int j = 0; j < 4; j++) {
            int n = wn*32 + j*8;
            unsigned b_h[2] = { Bh[tig][n+gid], Bh[tig+4][n+gid] };
            unsigned b_l[2] = { Bl[tig][n+gid], Bl[tig+4][n+gid] };
            #pragma unroll
            for (int i = 0; i < 2; i++) {
                mma16(acc[i][j], a_h[i], b_h);
                mma16(acc[i][j], a_h[i], b_l);
                mma16(acc[i][j], a_l[i], b_h);
            }
        }
        __syncthreads();
    }
    #pragma unroll
    for (int j = 0; j < 4; j++) {
        int n = wn*32 + j*8 + 2*tig;
        #pragma unroll
        for (int i = 0; i < 2; i++) {
            int r = row0 + wm*32 + i*16 + gid;
            atomicAdd(&g_acc[r*HL + n],         acc[i][j][0]);
            atomicAdd(&g_acc[r*HL + n + 1],     acc[i][j][1]);
            atomicAdd(&g_acc[(r+8)*HL + n],     acc[i][j][2]);
            atomicAdd(&g_acc[(r+8)*HL + n + 1], acc[i][j][3]);
        }
    }
}

// ================= epilogue =================
__global__ void k_final(const float* __restrict__ b1, const float* __restrict__ W2,
                        const float* __restrict__ b2, float* __restrict__ out) {
    int g = blockIdx.x*blockDim.x + threadIdx.x;
    if (g >= BG) return;
    float l0 = b2[0], l1 = b2[1];
    #pragma unroll 8
    for (int j = 0; j < HL; j++) {
        float h = fmaxf(g_acc[g*HL + j] + b1[j], 0.0f);
        l0 = fmaf(h, W2[j*2 + 0], l0);
        l1 = fmaf(h, W2[j*2 + 1], l1);
    }
    float m = fmaxf(l0, l1);
    float lse = m + logf(expf(l0 - m) + expf(l1 - m));
    out[g*2 + 0] = l0 - lse;
    out[g*2 + 1] = l1 - lse;
}

// ================= launch =================
extern "C" void kernel_launch(void* const* d_in, const int* in_sizes, int n_in,
                              void* d_out, int out_size) {
    const float* x      = (const float*)d_in[0];
    const float* eattr  = (const float*)d_in[1];
    const float* W1     = (const float*)d_in[2];
    const float* b1     = (const float*)d_in[3];
    const float* W2     = (const float*)d_in[4];
    const float* b2     = (const float*)d_in[5];
    const float* W3     = (const float*)d_in[6];
    const float* b3     = (const float*)d_in[7];
    const float* lin1W  = (const float*)d_in[8];
    const float* lin1b  = (const float*)d_in[9];
    const float* lin2W  = (const float*)d_in[10];
    const float* lin2b  = (const float*)d_in[11];
    const int*   eidx   = (const int*)d_in[12];
    float*       out    = (float*)d_out;

    k_prep<<<BG, 256>>>(x, eattr, eidx);
    k_gemm_conv<FIN><<<NN/128, 256>>>(W1, b1, 0);
    k_aggregate<<<BG, 256>>>(0);
    k_gemm_conv<HH><<<NN/128, 256>>>(W2, b2, HH);
    k_aggregate<<<BG, 256>>>(HH);
    k_gemm_conv<HH><<<NN/128, 256>>>(W3, b3, 2*HH);
    dim3 g1(BG/128, 45);
    k_lin1<<<g1, 256>>>(lin1W);
    k_final<<<(BG + 255)/256, 256>>>(lin1b, lin2W, lin2b, out);
}

// round 6
// speedup vs baseline: 1.4213x; 1.0852x over previous
#include <cuda_runtime.h>
#include <cuda_bf16.h>
#include <math.h>

#define NN     46080
#define EE     737280
#define BG     512
#define NODES  90
#define EPG    1440
#define FIN    90
#define HH     128
#define HL     64
#define XCW    (3*HH)       // 384
#define LDA1   (NODES*XCW)  // 34560

// ---------------- device scratch ----------------
__device__ float g_dis[NN];
__device__ int   g_off[NN];
__device__ int   g_cnt[NN];
__device__ int   g_csrc[EE];     // LOCAL source index (0..89)
__device__ float g_cnorm[EE];
__device__ float g_agg[NN*HH];
__device__ float g_xc[NN*XCW];   // [h1|h2|h3]; viewed as z [512, 34560]
__device__ float g_acc[BG*HL];

// ---------------- bf16 split helpers ----------------
__device__ __forceinline__ void f2bf2(float v0, float v1, unsigned &h, unsigned &l) {
    __nv_bfloat16 h0 = __float2bfloat16(v0), h1 = __float2bfloat16(v1);
    float r0 = v0 - __bfloat162float(h0);
    float r1 = v1 - __bfloat162float(h1);
    __nv_bfloat16 l0 = __float2bfloat16(r0), l1 = __float2bfloat16(r1);
    h = ((unsigned)__bfloat16_as_ushort(h1) << 16) | (unsigned)__bfloat16_as_ushort(h0);
    l = ((unsigned)__bfloat16_as_ushort(l1) << 16) | (unsigned)__bfloat16_as_ushort(l0);
}
__device__ __forceinline__ void mma16(float* c, const unsigned* a, const unsigned* b) {
    asm volatile("mma.sync.aligned.m16n8k16.row.col.f32.bf16.bf16.f32 "
        "{%0,%1,%2,%3}, {%4,%5,%6,%7}, {%8,%9}, {%0,%1,%2,%3};"
        : "+f"(c[0]), "+f"(c[1]), "+f"(c[2]), "+f"(c[3])
        : "r"(a[0]), "r"(a[1]), "r"(a[2]), "r"(a[3]), "r"(b[0]), "r"(b[1]));
}

// ================= prologue: per-graph CSR build + dis + layer-1 aggregation =================
__global__ void k_prep(const float* __restrict__ x, const float* __restrict__ eattr,
                       const int* __restrict__ ei) {
    __shared__ float sdeg[NODES];
    __shared__ float sdis[NODES];
    __shared__ int   scnt[NODES];
    __shared__ int   soff[NODES];
    __shared__ int   scur[NODES];
    __shared__ short ssrc[EPG];
    __shared__ float snorm[EPG];
    __shared__ float sx[NODES*FIN];

    const int g = blockIdx.x;
    const int t = threadIdx.x;
    const int ebase = g*EPG;

    if (t < NODES) { sdeg[t] = 1.0f; scnt[t] = 0; scur[t] = 0; }
    if (t < HL) g_acc[g*HL + t] = 0.0f;
    __syncthreads();

    for (int e = t; e < EPG; e += blockDim.x) {
        int d = ei[EE + ebase + e] - g*NODES;
        atomicAdd(&sdeg[d], eattr[ebase + e]);
        atomicAdd(&scnt[d], 1);
    }
    __syncthreads();
    if (t < NODES) sdis[t] = rsqrtf(sdeg[t]);
    __syncthreads();
    if (t == 0) {
        int acc = 0;
        #pragma unroll 1
        for (int n = 0; n < NODES; n++) { soff[n] = acc; acc += scnt[n]; }
    }
    __syncthreads();
    for (int e = t; e < EPG; e += blockDim.x) {
        int s = ei[ebase + e] - g*NODES;
        int d = ei[EE + ebase + e] - g*NODES;
        int p = soff[d] + atomicAdd(&scur[d], 1);
        float nm = sdis[s] * eattr[ebase + e] * sdis[d];
        ssrc[p] = (short)s;  snorm[p] = nm;
        g_csrc[ebase + p] = s;  g_cnorm[ebase + p] = nm;
    }
    if (t < NODES) {
        g_dis[g*NODES + t] = sdis[t];
        g_off[g*NODES + t] = ebase + soff[t];
        g_cnt[g*NODES + t] = scnt[t];
    }
    const float* gx = x + (long)g*NODES*FIN;
    for (int i = t; i < NODES*FIN; i += blockDim.x) sx[i] = gx[i];
    __syncthreads();

    int warp = t >> 5, lane = t & 31;
    for (int node = warp; node < NODES; node += (blockDim.x >> 5)) {
        float selfnm = sdis[node]*sdis[node];
        float acc[3];
        #pragma unroll
        for (int j = 0; j < 3; j++) {
            int f = lane + 32*j;
            acc[j] = (f < FIN) ? selfnm * sx[node*FIN + f] : 0.0f;
        }
        int o = soff[node], c = scnt[node];
        for (int p = o; p < o + c; p++) {
            int sl = ssrc[p];
            float nm = snorm[p];
            #pragma unroll
            for (int j = 0; j < 3; j++) {
                int f = lane + 32*j;
                if (f < FIN) acc[j] = fmaf(nm, sx[sl*FIN + f], acc[j]);
            }
        }
        #pragma unroll
        for (int j = 0; j < 3; j++) {
            int f = lane + 32*j;
            if (f < FIN) g_agg[(g*NODES + node)*FIN + f] = acc[j];
        }
    }
}

// ================= aggregation for layers 2/3 =================
__global__ void k_aggregate(int colOff) {
    __shared__ float sh[NODES*HH];
    int g = blockIdx.x;
    const float* gin = g_xc + (long)g * NODES * XCW + colOff;
    for (int idx = threadIdx.x; idx < NODES*HH; idx += blockDim.x) {
        int r = idx >> 7, c = idx & 127;
        sh[idx] = gin[r*XCW + c];
    }
    __syncthreads();

    int warp = threadIdx.x >> 5, lane = threadIdx.x & 31;
    for (int node = warp; node < NODES; node += (blockDim.x >> 5)) {
        int gi = g*NODES + node;
        float ds = g_dis[gi];
        float selfnm = ds*ds;
        float acc[4];
        #pragma unroll
        for (int j = 0; j < 4; j++) acc[j] = selfnm * sh[node*HH + lane + 32*j];
        int o = g_off[gi], c = g_cnt[gi];
        for (int p = o; p < o + c; p++) {
            int sl = g_csrc[p];
            float nm = g_cnorm[p];
            #pragma unroll
            for (int j = 0; j < 4; j++)
                acc[j] = fmaf(nm, sh[sl*HH + lane + 32*j], acc[j]);
        }
        #pragma unroll
        for (int j = 0; j < 4; j++) g_agg[gi*HH + lane + 32*j] = acc[j];
    }
}

// ================= conv GEMM (bf16 split-3, software-pipelined) =================
// CTA: 256 thr (8 warps, 4x2), tile M=128 N=128, KB=16, double-buffered smem.
template<int K>
__global__ void __launch_bounds__(256, 2) k_gemm_conv(const float* __restrict__ W,
                                                      const float* __restrict__ bias,
                                                      int colOff) {
    __shared__ unsigned Ah[2][8][132], Al[2][8][132];
    __shared__ unsigned Bh[2][8][132], Bl[2][8][132];
    const int t = threadIdx.x, lane = t & 31, wid = t >> 5;
    const int wm = wid >> 1, wn = wid & 1;
    const int gid = lane >> 2, tig = lane & 3;
    const int row0 = blockIdx.x * 128;
    const int KT = (K + 15) / 16;

    // per-thread load coordinates (constant across tiles)
    const int amj[4] = { (t*4+0) >> 3, (t*4+1) >> 3, (t*4+2) >> 3, (t*4+3) >> 3 };
    const int akj[4] = { (t*4+0) & 7,  (t*4+1) & 7,  (t*4+2) & 7,  (t*4+3) & 7 };
    const int bnj[4] = { (t*4+0) & 127, (t*4+1) & 127, (t*4+2) & 127, (t*4+3) & 127 };
    const int bkj[4] = { (t*4+0) >> 7,  (t*4+1) >> 7,  (t*4+2) >> 7,  (t*4+3) >> 7 };

    float rA[4][2], rB[4][2];
    auto load_tile = [&](int kt) {
        int k0 = kt * 16;
        #pragma unroll
        for (int j = 0; j < 4; j++) {
            int ka = k0 + 2*akj[j];
            const float* p = &g_agg[(long)(row0 + amj[j])*K + ka];
            rA[j][0] = (K % 16 == 0 || ka     < K) ? p[0] : 0.0f;
            rA[j][1] = (K % 16 == 0 || ka + 1 < K) ? p[1] : 0.0f;
        }
        #pragma unroll
        for (int j = 0; j < 4; j++) {
            int ka = k0 + 2*bkj[j];
            rB[j][0] = (K % 16 == 0 || ka     < K) ? W[ka*HH + bnj[j]]     : 0.0f;
            rB[j][1] = (K % 16 == 0 || ka + 1 < K) ? W[(ka+1)*HH + bnj[j]] : 0.0f;
        }
    };

    float acc[2][8][4];
    #pragma unroll
    for (int i = 0; i < 2; i++)
        #pragma unroll
        for (int j = 0; j < 8; j++)
            #pragma unroll
            for (int q = 0; q < 4; q++) acc[i][j][q] = 0.0f;

    load_tile(0);
    for (int kt = 0; kt < KT; kt++) {
        int buf = kt & 1;
        #pragma unroll
        for (int j = 0; j < 4; j++) {
            unsigned h, l;
            f2bf2(rA[j][0], rA[j][1], h, l);
            Ah[buf][akj[j]][amj[j]] = h; Al[buf][akj[j]][amj[j]] = l;
        }
        #pragma unroll
        for (int j = 0; j < 4; j++) {
            unsigned h, l;
            f2bf2(rB[j][0], rB[j][1], h, l);
            Bh[buf][bkj[j]][bnj[j]] = h; Bl[buf][bkj[j]][bnj[j]] = l;
        }
        __syncthreads();
        if (kt + 1 < KT) load_tile(kt + 1);   // LDGs overlap MMA section below

        unsigned a_h[2][4], a_l[2][4];
        #pragma unroll
        for (int i = 0; i < 2; i++) {
            int m = wm*32 + i*16;
            a_h[i][0] = Ah[buf][tig  ][m+gid]; a_h[i][1] = Ah[buf][tig  ][m+gid+8];
            a_h[i][2] = Ah[buf][tig+4][m+gid]; a_h[i][3] = Ah[buf][tig+4][m+gid+8];
            a_l[i][0] = Al[buf][tig  ][m+gid]; a_l[i][1] = Al[buf][tig  ][m+gid+8];
            a_l[i][2] = Al[buf][tig+4][m+gid]; a_l[i][3] = Al[buf][tig+4][m+gid+8];
        }
        #pragma unroll
        for (int j = 0; j < 8; j++) {
            int n = wn*64 + j*8;
            unsigned b_h[2] = { Bh[buf][tig][n+gid], Bh[buf][tig+4][n+gid] };
            unsigned b_l[2] = { Bl[buf][tig][n+gid], Bl[buf][tig+4][n+gid] };
            #pragma unroll
            for (int i = 0; i < 2; i++) {
                mma16(acc[i][j], a_h[i], b_h);
                mma16(acc[i][j], a_h[i], b_l);
                mma16(acc[i][j], a_l[i], b_h);
            }
        }
        // no trailing sync: next iter writes the other buffer; the sync above
        // guarantees no warp still reads it (see pipelining proof).
    }
    #pragma unroll
    for (int j = 0; j < 8; j++) {
        int n = wn*64 + j*8 + 2*tig;
        float b0 = bias[n], b1 = bias[n+1];
        #pragma unroll
        for (int i = 0; i < 2; i++) {
            int r = row0 + wm*32 + i*16 + gid;
            float2 v0 = { fmaxf(acc[i][j][0] + b0, 0.0f), fmaxf(acc[i][j][1] + b1, 0.0f) };
            float2 v1 = { fmaxf(acc[i][j][2] + b0, 0.0f), fmaxf(acc[i][j][3] + b1, 0.0f) };
            *(float2*)&g_xc[(long)r*XCW + colOff + n]     = v0;
            *(float2*)&g_xc[(long)(r+8)*XCW + colOff + n] = v1;
        }
    }
}

// ================= lin1 (bf16 split-3, split-K, software-pipelined) =================
// CTA: 256 thr (8 warps, 4x2), tile M=128 N=64, K-chunk 384 (24 k-tiles), grid (4, 90).
__global__ void __launch_bounds__(256, 2) k_lin1(const float* __restrict__ W) {
    __shared__ unsigned Ah[2][8][132], Al[2][8][132];
    __shared__ unsigned Bh[2][8][68],  Bl[2][8][68];
    const int t = threadIdx.x, lane = t & 31, wid = t >> 5;
    const int wm = wid >> 1, wn = wid & 1;
    const int gid = lane >> 2, tig = lane & 3;
    const int row0  = blockIdx.x * 128;
    const int kbase = blockIdx.y * 384;
    const int KT = 24;

    const int amj[4] = { (t*4+0) >> 3, (t*4+1) >> 3, (t*4+2) >> 3, (t*4+3) >> 3 };
    const int akj[4] = { (t*4+0) & 7,  (t*4+1) & 7,  (t*4+2) & 7,  (t*4+3) & 7 };
    const int bnj[2] = { (t*2+0) & 63, (t*2+1) & 63 };
    const int bkj[2] = { (t*2+0) >> 6, (t*2+1) >> 6 };

    float rA[4][2], rB[2][2];
    auto load_tile = [&](int kt) {
        int k0 = kbase + kt * 16;
        #pragma unroll
        for (int j = 0; j < 4; j++) {
            const float* p = &g_xc[(long)(row0 + amj[j])*LDA1 + k0 + 2*akj[j]];
            rA[j][0] = p[0]; rA[j][1] = p[1];
        }
        #pragma unroll
        for (int j = 0; j < 2; j++) {
            int ka = k0 + 2*bkj[j];
            rB[j][0] = W[ka*HL + bnj[j]];
            rB[j][1] = W[(ka+1)*HL + bnj[j]];
        }
    };

    float acc[2][4][4];
    #pragma unroll
    for (int i = 0; i < 2; i++)
        #pragma unroll
        for (int j = 0; j < 4; j++)
            #pragma unroll
            for (int q = 0; q < 4; q++) acc[i][j][q] = 0.0f;

    load_tile(0);
    for (int kt = 0; kt < KT; kt++) {
        int buf = kt & 1;
        #pragma unroll
        for (int j = 0; j < 4; j++) {
            unsigned h, l;
            f2bf2(rA[j][0], rA[j][1], h, l);
            Ah[buf][akj[j]][amj[j]] = h; Al[buf][akj[j]][amj[j]] = l;
        }
        #pragma unroll
        for (int j = 0; j < 2; j++) {
            unsigned h, l;
            f2bf2(rB[j][0], rB[j][1], h, l);
            Bh[buf][bkj[j]][bnj[j]] = h; Bl[buf][bkj[j]][bnj[j]] = l;
        }
        __syncthreads();
        if (kt + 1 < KT) load_tile(kt + 1);

        unsigned a_h[2][4], a_l[2][4];
        #pragma unroll
        for (int i = 0; i < 2; i++) {
            int m = wm*32 + i*16;
            a_h[i][0] = Ah[buf][tig  ][m+gid]; a_h[i][1] = Ah[buf][tig  ][m+gid+8];
            a_h[i][2] = Ah[buf][tig+4][m+gid]; a_h[i][3] = Ah[buf][tig+4][m+gid+8];
            a_l[i][0] = Al[buf][tig  ][m+gid]; a_l[i][1] = Al[buf][tig  ][m+gid+8];
            a_l[i][2] = Al[buf][tig+4][m+gid]; a_l[i][3] = Al[buf][tig+4][m+gid+8];
        }
        #pragma unroll
        for (int j = 0; j < 4; j++) {
            int n = wn*32 + j*8;
            unsigned b_h[2] = { Bh[buf][tig][n+gid], Bh[buf][tig+4][n+gid] };
            unsigned b_l[2] = { Bl[buf][tig][n+gid], Bl[buf][tig+4][n+gid] };
            #pragma unroll
            for (int i = 0; i < 2; i++) {
                mma16(acc[i][j], a_h[i], b_h);
                mma16(acc[i][j], a_h[i], b_l);
                mma16(acc[i][j], a_l[i], b_h);
            }
        }
    }
    #pragma unroll
    for (int j = 0; j < 4; j++) {
        int n = wn*32 + j*8 + 2*tig;
        #pragma unroll
        for (int i = 0; i < 2; i++) {
            int r = row0 + wm*32 + i*16 + gid;
            atomicAdd(&g_acc[r*HL + n],         acc[i][j][0]);
            atomicAdd(&g_acc[r*HL + n + 1],     acc[i][j][1]);
            atomicAdd(&g_acc[(r+8)*HL + n],     acc[i][j][2]);
            atomicAdd(&g_acc[(r+8)*HL + n + 1], acc[i][j][3]);
        }
    }
}

// ================= epilogue =================
__global__ void k_final(const float* __restrict__ b1, const float* __restrict__ W2,
                        const float* __restrict__ b2, float* __restrict__ out) {
    int g = blockIdx.x*blockDim.x + threadIdx.x;
    if (g >= BG) return;
    float l0 = b2[0], l1 = b2[1];
    #pragma unroll 8
    for (int j = 0; j < HL; j++) {
        float h = fmaxf(g_acc[g*HL + j] + b1[j], 0.0f);
        l0 = fmaf(h, W2[j*2 + 0], l0);
        l1 = fmaf(h, W2[j*2 + 1], l1);
    }
    float m = fmaxf(l0, l1);
    float lse = m + logf(expf(l0 - m) + expf(l1 - m));
    out[g*2 + 0] = l0 - lse;
    out[g*2 + 1] = l1 - lse;
}

// ================= launch =================
extern "C" void kernel_launch(void* const* d_in, const int* in_sizes, int n_in,
                              void* d_out, int out_size) {
    const float* x      = (const float*)d_in[0];
    const float* eattr  = (const float*)d_in[1];
    const float* W1     = (const float*)d_in[2];
    const float* b1     = (const float*)d_in[3];
    const float* W2     = (const float*)d_in[4];
    const float* b2     = (const float*)d_in[5];
    const float* W3     = (const float*)d_in[6];
    const float* b3     = (const float*)d_in[7];
    const float* lin1W  = (const float*)d_in[8];
    const float* lin1b  = (const float*)d_in[9];
    const float* lin2W  = (const float*)d_in[10];
    const float* lin2b  = (const float*)d_in[11];
    const int*   eidx   = (const int*)d_in[12];
    float*       out    = (float*)d_out;

    k_prep<<<BG, 256>>>(x, eattr, eidx);
    k_gemm_conv<FIN><<<NN/128, 256>>>(W1, b1, 0);
    k_aggregate<<<BG, 256>>>(0);
    k_gemm_conv<HH><<<NN/128, 256>>>(W2, b2, HH);
    k_aggregate<<<BG, 256>>>(HH);
    k_gemm_conv<HH><<<NN/128, 256>>>(W3, b3, 2*HH);
    dim3 g1(BG/128, 90);   // split-K: KC=384
    k_lin1<<<g1, 256>>>(lin1W);
    k_final<<<(BG + 255)/256, 256>>>(lin1b, lin2W, lin2b, out);
}

// round 7
// speedup vs baseline: 1.4787x; 1.0404x over previous
#include <cuda_runtime.h>
#include <cuda_bf16.h>
#include <math.h>

#define NN     46080
#define EE     737280
#define BG     512
#define NODES  90
#define EPG    1440
#define HH     128
#define HL     64
#define XCW    (3*HH)       // 384
#define LDA1   (NODES*XCW)  // 34560
#define APAD   132

// ---------------- device scratch ----------------
__device__ float g_xc[NN*XCW];   // [h1|h2|h3]; viewed as z [512, 34560]
__device__ float g_acc[BG*HL];   // lin1 split-K accumulator

// ---------------- bf16 split helpers ----------------
__device__ __forceinline__ void f2bf2(float v0, float v1, unsigned &h, unsigned &l) {
    __nv_bfloat16 h0 = __float2bfloat16(v0), h1 = __float2bfloat16(v1);
    float r0 = v0 - __bfloat162float(h0);
    float r1 = v1 - __bfloat162float(h1);
    __nv_bfloat16 l0 = __float2bfloat16(r0), l1 = __float2bfloat16(r1);
    h = ((unsigned)__bfloat16_as_ushort(h1) << 16) | (unsigned)__bfloat16_as_ushort(h0);
    l = ((unsigned)__bfloat16_as_ushort(l1) << 16) | (unsigned)__bfloat16_as_ushort(l0);
}
__device__ __forceinline__ void mma16(float* c, const unsigned* a, const unsigned* b) {
    asm volatile("mma.sync.aligned.m16n8k16.row.col.f32.bf16.bf16.f32 "
        "{%0,%1,%2,%3}, {%4,%5,%6,%7}, {%8,%9}, {%0,%1,%2,%3};"
        : "+f"(c[0]), "+f"(c[1]), "+f"(c[2]), "+f"(c[3])
        : "r"(a[0]), "r"(a[1]), "r"(a[2]), "r"(a[3]), "r"(b[0]), "r"(b[1]));
}

// Shared memory layout (u32 units):
//  Aah [48*APAD], Aal [48*APAD]                 : adjacency pairs [k2=src/2][m=dst]
//  U   [2*64*APAD]  union:
//       Tah = U[0..], Tal = U[64*APAD..]        : T pairs [k2=feat/2][m=node]
//       Hbh = U[0..], Hbl = U[64*APAD..]        : H B-layout pairs [k2=node/2][n=feat]
//  F   [96*APAD] floats                          : Afp32 scratch, then H fp32 rows 0..89
//  Wb  [2][2][8*APAD]                            : W tile double buffer (h,l)
//  sdeg[96], sdis[96]
#define SM_A   (48*APAD)
#define SM_U   (2*64*APAD)
#define SM_F   (96*APAD)
#define SM_W   (2*2*8*APAD)
#define SMEM_U32 (2*SM_A + SM_U + SM_F + SM_W + 192)

// ================= fused per-graph GCN (3 layers) =================
__global__ void __launch_bounds__(512, 1) k_fused(
    const float* __restrict__ x, const float* __restrict__ eattr,
    const int* __restrict__ ei,
    const float* __restrict__ W1, const float* __restrict__ b1,
    const float* __restrict__ W2, const float* __restrict__ b2,
    const float* __restrict__ W3, const float* __restrict__ b3) {
    extern __shared__ unsigned smem[];
    unsigned* Aah = smem;
    unsigned* Aal = Aah + SM_A;
    unsigned* U   = Aal + SM_A;
    unsigned* Tah = U;
    unsigned* Tal = U + 64*APAD;
    unsigned* Hbh = U;                 // aliases Tah (phase-disjoint)
    unsigned* Hbl = U + 64*APAD;       // aliases Tal
    float*    F   = (float*)(U + SM_U);
    unsigned* Wb  = (unsigned*)(F + SM_F);   // [buf][hl][8*APAD]
    float* sdeg = (float*)(Wb + SM_W);
    float* sdis = sdeg + 96;

    const int g = blockIdx.x, t = threadIdx.x;
    const int lane = t & 31, wid = t >> 5;
    const int wm = wid >> 2, wn = wid & 3;          // 4x4 warp grid
    const int gid = lane >> 2, tig = lane & 3;
    const int ebase = g * EPG;

    if (t < HL) g_acc[g*HL + t] = 0.0f;

    // ---- dense normalized adjacency: F[k=src][m=dst] ----
    for (int i = t; i < SM_F; i += 512) F[i] = 0.0f;
    if (t < 96) sdeg[t] = 1.0f;
    __syncthreads();
    for (int e = t; e < EPG; e += 512)
        atomicAdd(&sdeg[ei[EE + ebase + e] - g*NODES], eattr[ebase + e]);
    __syncthreads();
    if (t < 96) sdis[t] = rsqrtf(sdeg[t]);
    __syncthreads();
    for (int e = t; e < EPG; e += 512) {
        int s = ei[ebase + e] - g*NODES;
        int d = ei[EE + ebase + e] - g*NODES;
        atomicAdd(&F[s*APAD + d], sdis[s] * eattr[ebase + e] * sdis[d]);
    }
    if (t < NODES) atomicAdd(&F[t*APAD + t], sdis[t]*sdis[t]);
    __syncthreads();
    // convert to bf16 split pairs [k2][m]
    for (int p = t; p < 48*128; p += 512) {
        int k2 = p >> 7, m = p & 127;
        float v0 = (m < NODES) ? F[(2*k2)*APAD + m]     : 0.0f;
        float v1 = (m < NODES) ? F[(2*k2 + 1)*APAD + m] : 0.0f;
        unsigned h, l; f2bf2(v0, v1, h, l);
        Aah[k2*APAD + m] = h; Aal[k2*APAD + m] = l;
    }

    const float* Ws[3] = {W1, W2, W3};
    const float* bs[3] = {b1, b2, b3};
    const int    KWs[3] = {90, HH, HH};

    float acc[2][4][4];

    for (int L = 0; L < 3; L++) {
        __syncthreads();   // prev layer fully done; U and F reusable
        // ---- build Hb [k2=node/2][n=feat] ----
        if (L == 0) {
            for (int p = t; p < 48*128; p += 512) {
                int k2 = p >> 7, n = p & 127;
                int n0 = 2*k2, n1 = 2*k2 + 1;
                float v0 = (n < 90 && n0 < NODES) ? x[((long)g*NODES + n0)*90 + n] : 0.0f;
                float v1 = (n < 90 && n1 < NODES) ? x[((long)g*NODES + n1)*90 + n] : 0.0f;
                unsigned h, l; f2bf2(v0, v1, h, l);
                Hbh[k2*APAD + n] = h; Hbl[k2*APAD + n] = l;
            }
        } else {
            for (int p = t; p < 48*128; p += 512) {
                int k2 = p >> 7, n = p & 127;
                int n0 = 2*k2, n1 = 2*k2 + 1;
                float v0 = (n0 < NODES) ? F[n0*APAD + n] : 0.0f;
                float v1 = (n1 < NODES) ? F[n1*APAD + n] : 0.0f;
                unsigned h, l; f2bf2(v0, v1, h, l);
                Hbh[k2*APAD + n] = h; Hbl[k2*APAD + n] = l;
            }
        }
        __syncthreads();

        // ---- GEMM1: T = A @ Hb   (M=128, N=128, K=96 -> 6 k16 tiles) ----
        #pragma unroll
        for (int i = 0; i < 2; i++)
            #pragma unroll
            for (int j = 0; j < 4; j++)
                #pragma unroll
                for (int q = 0; q < 4; q++) acc[i][j][q] = 0.0f;
        for (int kt = 0; kt < 6; kt++) {
            int r0 = (kt*8 + tig)*APAD, r4 = (kt*8 + tig + 4)*APAD;
            unsigned a_h[2][4], a_l[2][4];
            #pragma unroll
            for (int i = 0; i < 2; i++) {
                int m = wm*32 + i*16;
                a_h[i][0] = Aah[r0 + m+gid]; a_h[i][1] = Aah[r0 + m+gid+8];
                a_h[i][2] = Aah[r4 + m+gid]; a_h[i][3] = Aah[r4 + m+gid+8];
                a_l[i][0] = Aal[r0 + m+gid]; a_l[i][1] = Aal[r0 + m+gid+8];
                a_l[i][2] = Aal[r4 + m+gid]; a_l[i][3] = Aal[r4 + m+gid+8];
            }
            #pragma unroll
            for (int j = 0; j < 4; j++) {
                int n = wn*32 + j*8;
                unsigned b_h[2] = { Hbh[r0 + n+gid], Hbh[r4 + n+gid] };
                unsigned b_l[2] = { Hbl[r0 + n+gid], Hbl[r4 + n+gid] };
                #pragma unroll
                for (int i = 0; i < 2; i++) {
                    mma16(acc[i][j], a_h[i], b_h);
                    mma16(acc[i][j], a_h[i], b_l);
                    mma16(acc[i][j], a_l[i], b_h);
                }
            }
        }
        __syncthreads();   // Hb reads complete before Ta overwrites U

        // ---- T frags -> Ta pairs [k2=feat/2][m] ----
        #pragma unroll
        for (int j = 0; j < 4; j++) {
            int k2 = wn*16 + j*4 + tig;   // (wn*32 + j*8 + 2*tig)/2
            #pragma unroll
            for (int i = 0; i < 2; i++) {
                int m = wm*32 + i*16 + gid;
                unsigned h, l;
                f2bf2(acc[i][j][0], acc[i][j][1], h, l);
                Tah[k2*APAD + m] = h;  Tal[k2*APAD + m] = l;
                f2bf2(acc[i][j][2], acc[i][j][3], h, l);
                Tah[k2*APAD + m + 8] = h;  Tal[k2*APAD + m + 8] = l;
            }
        }
        __syncthreads();

        // ---- GEMM2: H = Ta @ W   (M=128, N=128, K=128 -> 8 k16 tiles, W streamed) ----
        const float* W = Ws[L];
        const int KW = KWs[L];
        #pragma unroll
        for (int i = 0; i < 2; i++)
            #pragma unroll
            for (int j = 0; j < 4; j++)
                #pragma unroll
                for (int q = 0; q < 4; q++) acc[i][j][q] = 0.0f;

        float rW[2][2];
        const int wk2[2] = { (t      ) >> 7, (t + 512) >> 7 };
        const int wnn[2] = { (t      ) & 127, (t + 512) & 127 };
        auto load_w = [&](int kt) {
            #pragma unroll
            for (int q = 0; q < 2; q++) {
                int k0 = kt*16 + 2*wk2[q];
                rW[q][0] = (k0     < KW) ? W[k0*HH + wnn[q]]       : 0.0f;
                rW[q][1] = (k0 + 1 < KW) ? W[(k0 + 1)*HH + wnn[q]] : 0.0f;
            }
        };
        load_w(0);
        for (int kt = 0; kt < 8; kt++) {
            int buf = kt & 1;
            unsigned* Wh = Wb + buf*(2*8*APAD);
            unsigned* Wl = Wh + 8*APAD;
            #pragma unroll
            for (int q = 0; q < 2; q++) {
                unsigned h, l; f2bf2(rW[q][0], rW[q][1], h, l);
                Wh[wk2[q]*APAD + wnn[q]] = h; Wl[wk2[q]*APAD + wnn[q]] = l;
            }
            __syncthreads();
            if (kt + 1 < 8) load_w(kt + 1);

            int r0 = (kt*8 + tig)*APAD, r4 = (kt*8 + tig + 4)*APAD;
            unsigned a_h[2][4], a_l[2][4];
            #pragma unroll
            for (int i = 0; i < 2; i++) {
                int m = wm*32 + i*16;
                a_h[i][0] = Tah[r0 + m+gid]; a_h[i][1] = Tah[r0 + m+gid+8];
                a_h[i][2] = Tah[r4 + m+gid]; a_h[i][3] = Tah[r4 + m+gid+8];
                a_l[i][0] = Tal[r0 + m+gid]; a_l[i][1] = Tal[r0 + m+gid+8];
                a_l[i][2] = Tal[r4 + m+gid]; a_l[i][3] = Tal[r4 + m+gid+8];
            }
            int s0 = tig*APAD, s4 = (tig + 4)*APAD;
            #pragma unroll
            for (int j = 0; j < 4; j++) {
                int n = wn*32 + j*8;
                unsigned b_h[2] = { Wh[s0 + n+gid], Wh[s4 + n+gid] };
                unsigned b_l[2] = { Wl[s0 + n+gid], Wl[s4 + n+gid] };
                #pragma unroll
                for (int i = 0; i < 2; i++) {
                    mma16(acc[i][j], a_h[i], b_h);
                    mma16(acc[i][j], a_h[i], b_l);
                    mma16(acc[i][j], a_l[i], b_h);
                }
            }
            // no trailing sync (double buffer; see pipeline invariant)
        }

        // ---- epilogue: relu(+bias) -> F (fp32 H) and g_xc ----
        const float* bias = bs[L];
        const int colOff = L * HH;
        #pragma unroll
        for (int j = 0; j < 4; j++) {
            int n = wn*32 + j*8 + 2*tig;
            float bb0 = bias[n], bb1 = bias[n+1];
            #pragma unroll
            for (int i = 0; i < 2; i++) {
                int m = wm*32 + i*16 + gid;
                float v0 = fmaxf(acc[i][j][0] + bb0, 0.0f);
                float v1 = fmaxf(acc[i][j][1] + bb1, 0.0f);
                float v2 = fmaxf(acc[i][j][2] + bb0, 0.0f);
                float v3 = fmaxf(acc[i][j][3] + bb1, 0.0f);
                if (m < NODES) {
                    F[m*APAD + n] = v0;  F[m*APAD + n + 1] = v1;
                    *(float2*)&g_xc[(long)(g*NODES + m)*XCW + colOff + n] = make_float2(v0, v1);
                }
                if (m + 8 < NODES) {
                    F[(m+8)*APAD + n] = v2;  F[(m+8)*APAD + n + 1] = v3;
                    *(float2*)&g_xc[(long)(g*NODES + m + 8)*XCW + colOff + n] = make_float2(v2, v3);
                }
            }
        }
    }
}

// ================= lin1 (bf16 split-3, split-K, pipelined) =================
// tile M=128 N=64, K-chunk 192 (12 k-tiles), grid (4, 180).
__global__ void __launch_bounds__(256, 2) k_lin1(const float* __restrict__ W) {
    __shared__ unsigned Ah[2][8][132], Al[2][8][132];
    __shared__ unsigned Bh[2][8][68],  Bl[2][8][68];
    const int t = threadIdx.x, lane = t & 31, wid = t >> 5;
    const int wm = wid >> 1, wn = wid & 1;
    const int gid = lane >> 2, tig = lane & 3;
    const int row0  = blockIdx.x * 128;
    const int kbase = blockIdx.y * 192;
    const int KT = 12;

    const int amj[4] = { (t*4+0) >> 3, (t*4+1) >> 3, (t*4+2) >> 3, (t*4+3) >> 3 };
    const int akj[4] = { (t*4+0) & 7,  (t*4+1) & 7,  (t*4+2) & 7,  (t*4+3) & 7 };
    const int bnj[2] = { (t*2+0) & 63, (t*2+1) & 63 };
    const int bkj[2] = { (t*2+0) >> 6, (t*2+1) >> 6 };

    float rA[4][2], rB[2][2];
    auto load_tile = [&](int kt) {
        int k0 = kbase + kt * 16;
        #pragma unroll
        for (int j = 0; j < 4; j++) {
            const float* p = &g_xc[(long)(row0 + amj[j])*LDA1 + k0 + 2*akj[j]];
            rA[j][0] = p[0]; rA[j][1] = p[1];
        }
        #pragma unroll
        for (int j = 0; j < 2; j++) {
            int ka = k0 + 2*bkj[j];
            rB[j][0] = W[ka*HL + bnj[j]];
            rB[j][1] = W[(ka+1)*HL + bnj[j]];
        }
    };

    float acc[2][4][4];
    #pragma unroll
    for (int i = 0; i < 2; i++)
        #pragma unroll
        for (int j = 0; j < 4; j++)
            #pragma unroll
            for (int q = 0; q < 4; q++) acc[i][j][q] = 0.0f;

    load_tile(0);
    for (int kt = 0; kt < KT; kt++) {
        int buf = kt & 1;
        #pragma unroll
        for (int j = 0; j < 4; j++) {
            unsigned h, l; f2bf2(rA[j][0], rA[j][1], h, l);
            Ah[buf][akj[j]][amj[j]] = h; Al[buf][akj[j]][amj[j]] = l;
        }
        #pragma unroll
        for (int j = 0; j < 2; j++) {
            unsigned h, l; f2bf2(rB[j][0], rB[j][1], h, l);
            Bh[buf][bkj[j]][bnj[j]] = h; Bl[buf][bkj[j]][bnj[j]] = l;
        }
        __syncthreads();
        if (kt + 1 < KT) load_tile(kt + 1);

        unsigned a_h[2][4], a_l[2][4];
        #pragma unroll
        for (int i = 0; i < 2; i++) {
            int m = wm*32 + i*16;
            a_h[i][0] = Ah[buf][tig  ][m+gid]; a_h[i][1] = Ah[buf][tig  ][m+gid+8];
            a_h[i][2] = Ah[buf][tig+4][m+gid]; a_h[i][3] = Ah[buf][tig+4][m+gid+8];
            a_l[i][0] = Al[buf][tig  ][m+gid]; a_l[i][1] = Al[buf][tig  ][m+gid+8];
            a_l[i][2] = Al[buf][tig+4][m+gid]; a_l[i][3] = Al[buf][tig+4][m+gid+8];
        }
        #pragma unroll
        for (int j = 0; j < 4; j++) {
            int n = wn*32 + j*8;
            unsigned b_h[2] = { Bh[buf][tig][n+gid], Bh[buf][tig+4][n+gid] };
            unsigned b_l[2] = { Bl[buf][tig][n+gid], Bl[buf][tig+4][n+gid] };
            #pragma unroll
            for (int i = 0; i < 2; i++) {
                mma16(acc[i][j], a_h[i], b_h);
                mma16(acc[i][j], a_h[i], b_l);
                mma16(acc[i][j], a_l[i], b_h);
            }
        }
    }
    #pragma unroll
    for (int j = 0; j < 4; j++) {
        int n = wn*32 + j*8 + 2*tig;
        #pragma unroll
        for (int i = 0; i < 2; i++) {
            int r = row0 + wm*32 + i*16 + gid;
            atomicAdd(&g_acc[r*HL + n],         acc[i][j][0]);
            atomicAdd(&g_acc[r*HL + n + 1],     acc[i][j][1]);
            atomicAdd(&g_acc[(r+8)*HL + n],     acc[i][j][2]);
            atomicAdd(&g_acc[(r+8)*HL + n + 1], acc[i][j][3]);
        }
    }
}

// ================= epilogue =================
__global__ void k_final(const float* __restrict__ b1, const float* __restrict__ W2,
                        const float* __restrict__ b2, float* __restrict__ out) {
    int g = blockIdx.x*blockDim.x + threadIdx.x;
    if (g >= BG) return;
    float l0 = b2[0], l1 = b2[1];
    #pragma unroll 8
    for (int j = 0; j < HL; j++) {
        float h = fmaxf(g_acc[g*HL + j] + b1[j], 0.0f);
        l0 = fmaf(h, W2[j*2 + 0], l0);
        l1 = fmaf(h, W2[j*2 + 1], l1);
    }
    float m = fmaxf(l0, l1);
    float lse = m + logf(expf(l0 - m) + expf(l1 - m));
    out[g*2 + 0] = l0 - lse;
    out[g*2 + 1] = l1 - lse;
}

// ================= launch =================
extern "C" void kernel_launch(void* const* d_in, const int* in_sizes, int n_in,
                              void* d_out, int out_size) {
    const float* x      = (const float*)d_in[0];
    const float* eattr  = (const float*)d_in[1];
    const float* W1     = (const float*)d_in[2];
    const float* b1     = (const float*)d_in[3];
    const float* W2     = (const float*)d_in[4];
    const float* b2     = (const float*)d_in[5];
    const float* W3     = (const float*)d_in[6];
    const float* b3     = (const float*)d_in[7];
    const float* lin1W  = (const float*)d_in[8];
    const float* lin1b  = (const float*)d_in[9];
    const float* lin2W  = (const float*)d_in[10];
    const float* lin2b  = (const float*)d_in[11];
    const int*   eidx   = (const int*)d_in[12];
    float*       out    = (float*)d_out;

    const int smem_bytes = SMEM_U32 * 4;   // ~182 KB
    static int attr_set = 0;
    if (!attr_set) {
        cudaFuncSetAttribute(k_fused, cudaFuncAttributeMaxDynamicSharedMemorySize, smem_bytes);
        attr_set = 1;
    }

    k_fused<<<BG, 512, smem_bytes>>>(x, eattr, eidx, W1, b1, W2, b2, W3, b3);
    dim3 g1(BG/128, 180);   // split-K: KC=192
    k_lin1<<<g1, 256>>>(lin1W);
    k_final<<<(BG + 255)/256, 256>>>(lin1b, lin2W, lin2b, out);
}

// round 9
// speedup vs baseline: 1.9467x; 1.3165x over previous
#include <cuda_runtime.h>
#include <cuda_bf16.h>
#include <math.h>

#define NN     46080
#define EE     737280
#define BG     512
#define NODES  90
#define EPG    1440
#define HH     128
#define HL     64
#define XCW    (3*HH)       // 384
#define LDA1   (NODES*XCW)  // 34560

#define MP 104              // m-stride (u32) for A/Ta  (104 % 32 == 8: conflict-free)
#define NP 136              // n-stride (u32) for Hb/W  (136 % 32 == 8)

// smem byte offsets
#define OFF_A0  1024
#define SZ_A    (48*MP*4)            // 19968
#define OFF_A1  (OFF_A0 + SZ_A)
#define OFF_U   (OFF_A1 + SZ_A)      // 40960
#define SZ_U    (2*64*MP*4)          // 53248 (max of Hb 52224 / Ta 53248 / F 39936)
#define OFF_W   (OFF_U + SZ_U)       // 94208
#define SZ_WB   (8*NP*4)             // 4352
#define SMEMB   (OFF_W + 4*SZ_WB)    // 111616 bytes (~109 KB) -> 2 CTAs/SM

// ---------------- device scratch ----------------
__device__ float g_xc[NN*XCW];   // [h1|h2|h3]; viewed as z [512, 34560]
__device__ float g_acc[BG*HL];   // lin1 split-K accumulator

// ---------------- bf16 split helpers ----------------
__device__ __forceinline__ void f2bf2(float v0, float v1, unsigned &h, unsigned &l) {
    __nv_bfloat16 h0 = __float2bfloat16(v0), h1 = __float2bfloat16(v1);
    float r0 = v0 - __bfloat162float(h0);
    float r1 = v1 - __bfloat162float(h1);
    __nv_bfloat16 l0 = __float2bfloat16(r0), l1 = __float2bfloat16(r1);
    h = ((unsigned)__bfloat16_as_ushort(h1) << 16) | (unsigned)__bfloat16_as_ushort(h0);
    l = ((unsigned)__bfloat16_as_ushort(l1) << 16) | (unsigned)__bfloat16_as_ushort(l0);
}
__device__ __forceinline__ void mma16(float* c, const unsigned* a, const unsigned* b) {
    asm volatile("mma.sync.aligned.m16n8k16.row.col.f32.bf16.bf16.f32 "
        "{%0,%1,%2,%3}, {%4,%5,%6,%7}, {%8,%9}, {%0,%1,%2,%3};"
        : "+f"(c[0]), "+f"(c[1]), "+f"(c[2]), "+f"(c[3])
        : "r"(a[0]), "r"(a[1]), "r"(a[2]), "r"(a[3]), "r"(b[0]), "r"(b[1]));
}

// ================= fused per-graph 3-layer GCN (mma.sync, M=96) =================
__global__ void __launch_bounds__(256, 2) k_fused(
    const float* __restrict__ x, const float* __restrict__ eattr,
    const int* __restrict__ ei,
    const float* __restrict__ W1, const float* __restrict__ b1,
    const float* __restrict__ W2, const float* __restrict__ b2,
    const float* __restrict__ W3, const float* __restrict__ b3) {
    extern __shared__ char sm[];
    float*    sdeg = (float*)sm;               // 96 @0
    float*    sdis = (float*)(sm + 512);       // 96 @512
    unsigned* Aah  = (unsigned*)(sm + OFF_A0); // [k2=48][m<=96] stride MP
    unsigned* Aal  = (unsigned*)(sm + OFF_A1);
    unsigned* HbH  = (unsigned*)(sm + OFF_U);                  // [k2=48][n=128] stride NP
    unsigned* HbL  = (unsigned*)(sm + OFF_U + 48*NP*4);
    unsigned* TaH  = (unsigned*)(sm + OFF_U);                  // [k2=64][m<=96] stride MP
    unsigned* TaL  = (unsigned*)(sm + OFF_U + 64*MP*4);
    float*    F    = (float*)(sm + OFF_U);                     // [96][96] stride MP (prologue only)
    unsigned* Wb   = (unsigned*)(sm + OFF_W);                  // [buf][hl][8*NP]

    const int g = blockIdx.x, t = threadIdx.x, lane = t & 31, wid = t >> 5;
    const int wm = wid >> 2, wn = wid & 3;      // 2 x 4 warps; warp tile 48x32
    const int gid = lane >> 2, tig = lane & 3;
    const int eb = g * EPG;

    if (t < HL) g_acc[g*HL + t] = 0.0f;

    // ---- prologue: dense normalized adjacency in F (aliases U) ----
    for (int i = t; i < 96*MP; i += 256) F[i] = 0.0f;
    if (t < 96) sdeg[t] = 1.0f;
    __syncthreads();
    for (int e = t; e < EPG; e += 256)
        atomicAdd(&sdeg[ei[EE + eb + e] - g*NODES], eattr[eb + e]);
    __syncthreads();
    if (t < 96) sdis[t] = rsqrtf(sdeg[t]);
    __syncthreads();
    for (int e = t; e < EPG; e += 256) {
        int s = ei[eb + e] - g*NODES;
        int d = ei[EE + eb + e] - g*NODES;
        atomicAdd(&F[d*MP + s], sdis[s] * eattr[eb + e] * sdis[d]);
    }
    if (t < NODES) atomicAdd(&F[t*MP + t], sdis[t]*sdis[t]);
    __syncthreads();
    // ---- A pairs [k2=src/2][m=dst] (rows/cols >=90 are zero in F already) ----
    for (int i = t; i < 48*96; i += 256) {
        int k2 = i / 96, m = i - 96*k2;
        unsigned h, l; f2bf2(F[m*MP + 2*k2], F[m*MP + 2*k2 + 1], h, l);
        Aah[k2*MP + m] = h; Aal[k2*MP + m] = l;
    }
    __syncthreads();   // F fully consumed before Hb0 overwrites U
    // ---- Hb0 = x^T pairs [k2=node/2][n=feat] ----
    for (int i = t; i < 48*128; i += 256) {
        int k2 = i >> 7, n = i & 127;
        int n0 = 2*k2, n1 = n0 + 1;
        float v0 = (n < 90 && n0 < 90) ? x[((long)g*NODES + n0)*90 + n] : 0.0f;
        float v1 = (n < 90 && n1 < 90) ? x[((long)g*NODES + n1)*90 + n] : 0.0f;
        unsigned h, l; f2bf2(v0, v1, h, l);
        HbH[k2*NP + n] = h; HbL[k2*NP + n] = l;
    }

    const float* Ws[3]  = {W1, W2, W3};
    const float* bs[3]  = {b1, b2, b3};
    const int    KT2s[3] = {6, 8, 8};
    float acc[3][4][4];

    for (int L = 0; L < 3; L++) {
        __syncthreads();   // Hb ready
        // ======== GEMM1: T[m=96][n=128] = A @ Hb, K=96 ========
        #pragma unroll
        for (int i = 0; i < 3; i++)
            #pragma unroll
            for (int j = 0; j < 4; j++)
                #pragma unroll
                for (int q = 0; q < 4; q++) acc[i][j][q] = 0.0f;
        for (int kt = 0; kt < 6; kt++) {
            int r0 = (kt*8 + tig)*MP, r4 = (kt*8 + tig + 4)*MP;
            int s0 = (kt*8 + tig)*NP, s4 = (kt*8 + tig + 4)*NP;
            unsigned a_h[3][4], a_l[3][4];
            #pragma unroll
            for (int i = 0; i < 3; i++) {
                int m = wm*48 + i*16;
                a_h[i][0] = Aah[r0 + m+gid]; a_h[i][1] = Aah[r0 + m+gid+8];
                a_h[i][2] = Aah[r4 + m+gid]; a_h[i][3] = Aah[r4 + m+gid+8];
                a_l[i][0] = Aal[r0 + m+gid]; a_l[i][1] = Aal[r0 + m+gid+8];
                a_l[i][2] = Aal[r4 + m+gid]; a_l[i][3] = Aal[r4 + m+gid+8];
            }
            #pragma unroll
            for (int j = 0; j < 4; j++) {
                int n = wn*32 + j*8;
                unsigned b_h[2] = { HbH[s0 + n+gid], HbH[s4 + n+gid] };
                unsigned b_l[2] = { HbL[s0 + n+gid], HbL[s4 + n+gid] };
                #pragma unroll
                for (int i = 0; i < 3; i++) {
                    mma16(acc[i][j], a_h[i], b_h);
                    mma16(acc[i][j], a_h[i], b_l);
                    mma16(acc[i][j], a_l[i], b_h);
                }
            }
        }
        __syncthreads();   // all Hb reads done; U reusable
        // ---- T -> Ta pairs [k2=feat/2][m] (pairs over feat: in-thread) ----
        #pragma unroll
        for (int j = 0; j < 4; j++) {
            int k2 = wn*16 + j*4 + tig;
            #pragma unroll
            for (int i = 0; i < 3; i++) {
                int m = wm*48 + i*16 + gid;
                unsigned h, l;
                f2bf2(acc[i][j][0], acc[i][j][1], h, l);
                TaH[k2*MP + m] = h; TaL[k2*MP + m] = l;
                f2bf2(acc[i][j][2], acc[i][j][3], h, l);
                TaH[k2*MP + m+8] = h; TaL[k2*MP + m+8] = l;
            }
        }
        // ======== GEMM2: H[m=96][n=128] = Ta @ W, K=96/128 (W streamed) ========
        #pragma unroll
        for (int i = 0; i < 3; i++)
            #pragma unroll
            for (int j = 0; j < 4; j++)
                #pragma unroll
                for (int q = 0; q < 4; q++) acc[i][j][q] = 0.0f;
        const float* W = Ws[L];
        const int KT2 = KT2s[L];
        float rW[4][2];
        auto loadw = [&](int kt) {
            #pragma unroll
            for (int q = 0; q < 4; q++) {
                int idx = t*4 + q; int n = idx & 127, k2 = idx >> 7;
                int k = kt*16 + 2*k2;
                rW[q][0] = (L > 0 || k     < 90) ? W[k*HH + n]     : 0.0f;
                rW[q][1] = (L > 0 || k + 1 < 90) ? W[(k+1)*HH + n] : 0.0f;
            }
        };
        loadw(0);
        for (int kt = 0; kt < KT2; kt++) {
            int buf = kt & 1;
            unsigned* Wh = Wb + buf*(2*8*NP);
            unsigned* Wl = Wh + 8*NP;
            #pragma unroll
            for (int q = 0; q < 4; q++) {
                int idx = t*4 + q; int n = idx & 127, k2 = idx >> 7;
                unsigned h, l; f2bf2(rW[q][0], rW[q][1], h, l);
                Wh[k2*NP + n] = h; Wl[k2*NP + n] = l;
            }
            __syncthreads();   // W tile ready (and, at kt=0, Ta ready)
            if (kt + 1 < KT2) loadw(kt + 1);

            int r0 = (kt*8 + tig)*MP, r4 = (kt*8 + tig + 4)*MP;
            int s0 = tig*NP, s4 = (tig + 4)*NP;
            unsigned a_h[3][4], a_l[3][4];
            #pragma unroll
            for (int i = 0; i < 3; i++) {
                int m = wm*48 + i*16;
                a_h[i][0] = TaH[r0 + m+gid]; a_h[i][1] = TaH[r0 + m+gid+8];
                a_h[i][2] = TaH[r4 + m+gid]; a_h[i][3] = TaH[r4 + m+gid+8];
                a_l[i][0] = TaL[r0 + m+gid]; a_l[i][1] = TaL[r0 + m+gid+8];
                a_l[i][2] = TaL[r4 + m+gid]; a_l[i][3] = TaL[r4 + m+gid+8];
            }
            #pragma unroll
            for (int j = 0; j < 4; j++) {
                int n = wn*32 + j*8;
                unsigned b_h[2] = { Wh[s0 + n+gid], Wh[s4 + n+gid] };
                unsigned b_l[2] = { Wl[s0 + n+gid], Wl[s4 + n+gid] };
                #pragma unroll
                for (int i = 0; i < 3; i++) {
                    mma16(acc[i][j], a_h[i], b_h);
                    mma16(acc[i][j], a_h[i], b_l);
                    mma16(acc[i][j], a_l[i], b_h);
                }
            }
            // no trailing sync (double-buffered W; Ta read-only here)
        }
        __syncthreads();   // all Ta reads done before Hb-next overwrites U
        // ---- epilogue: relu(+bias) -> g_xc; next Hb pairs via lane shuffles ----
        const float* bias = bs[L];
        #pragma unroll
        for (int i = 0; i < 3; i++) {
            #pragma unroll
            for (int j = 0; j < 4; j++) {
                int m = wm*48 + i*16 + gid;
                int n = wn*32 + j*8 + 2*tig;
                float b0 = bias[n], b1 = bias[n+1];
                float v0 = fmaxf(acc[i][j][0] + b0, 0.0f);
                float v1 = fmaxf(acc[i][j][1] + b1, 0.0f);
                float v2 = fmaxf(acc[i][j][2] + b0, 0.0f);
                float v3 = fmaxf(acc[i][j][3] + b1, 0.0f);
                if (m < NODES)
                    *(float2*)&g_xc[((long)g*NODES + m)*XCW + L*HH + n] = make_float2(v0, v1);
                if (m + 8 < NODES)
                    *(float2*)&g_xc[((long)g*NODES + m + 8)*XCW + L*HH + n] = make_float2(v2, v3);
                if (L < 2) {
                    float p0 = __shfl_down_sync(0xffffffffu, v0, 4);
                    float p1 = __shfl_down_sync(0xffffffffu, v1, 4);
                    float p2 = __shfl_down_sync(0xffffffffu, v2, 4);
                    float p3 = __shfl_down_sync(0xffffffffu, v3, 4);
                    if (!(gid & 1)) {   // even gid: owns node pair (m, m+1)
                        int k2 = wm*24 + i*8 + (gid >> 1);
                        unsigned h, l;
                        f2bf2(v0, p0, h, l); HbH[k2*NP + n]       = h; HbL[k2*NP + n]       = l;
                        f2bf2(v1, p1, h, l); HbH[k2*NP + n + 1]   = h; HbL[k2*NP + n + 1]   = l;
                        f2bf2(v2, p2, h, l); HbH[(k2+4)*NP + n]   = h; HbL[(k2+4)*NP + n]   = l;
                        f2bf2(v3, p3, h, l); HbH[(k2+4)*NP + n+1] = h; HbL[(k2+4)*NP + n+1] = l;
                    }
                }
            }
        }
    }
}

// ================= lin1 (bf16 split-3, split-K, pipelined) =================
__global__ void __launch_bounds__(256, 2) k_lin1(const float* __restrict__ W) {
    __shared__ unsigned Ah[2][8][132], Al[2][8][132];
    __shared__ unsigned Bh[2][8][68],  Bl[2][8][68];
    const int t = threadIdx.x, lane = t & 31, wid = t >> 5;
    const int wm = wid >> 1, wn = wid & 1;
    const int gid = lane >> 2, tig = lane & 3;
    const int row0  = blockIdx.x * 128;
    const int kbase = blockIdx.y * 192;
    const int KT = 12;

    const int amj[4] = { (t*4+0) >> 3, (t*4+1) >> 3, (t*4+2) >> 3, (t*4+3) >> 3 };
    const int akj[4] = { (t*4+0) & 7,  (t*4+1) & 7,  (t*4+2) & 7,  (t*4+3) & 7 };
    const int bnj[2] = { (t*2+0) & 63, (t*2+1) & 63 };
    const int bkj[2] = { (t*2+0) >> 6, (t*2+1) >> 6 };

    float rA[4][2], rB[2][2];
    auto load_tile = [&](int kt) {
        int k0 = kbase + kt * 16;
        #pragma unroll
        for (int j = 0; j < 4; j++) {
            const float* p = &g_xc[(long)(row0 + amj[j])*LDA1 + k0 + 2*akj[j]];
            rA[j][0] = p[0]; rA[j][1] = p[1];
        }
        #pragma unroll
        for (int j = 0; j < 2; j++) {
            int ka = k0 + 2*bkj[j];
            rB[j][0] = W[ka*HL + bnj[j]];
            rB[j][1] = W[(ka+1)*HL + bnj[j]];
        }
    };

    float acc[2][4][4];
    #pragma unroll
    for (int i = 0; i < 2; i++)
        #pragma unroll
        for (int j = 0; j < 4; j++)
            #pragma unroll
            for (int q = 0; q < 4; q++) acc[i][j][q] = 0.0f;

    load_tile(0);
    for (int kt = 0; kt < KT; kt++) {
        int buf = kt & 1;
        #pragma unroll
        for (int j = 0; j < 4; j++) {
            unsigned h, l; f2bf2(rA[j][0], rA[j][1], h, l);
            Ah[buf][akj[j]][amj[j]] = h; Al[buf][akj[j]][amj[j]] = l;
        }
        #pragma unroll
        for (int j = 0; j < 2; j++) {
            unsigned h, l; f2bf2(rB[j][0], rB[j][1], h, l);
            Bh[buf][bkj[j]][bnj[j]] = h; Bl[buf][bkj[j]][bnj[j]] = l;
        }
        __syncthreads();
        if (kt + 1 < KT) load_tile(kt + 1);

        unsigned a_h[2][4], a_l[2][4];
        #pragma unroll
        for (int i = 0; i < 2; i++) {
            int m = wm*32 + i*16;
            a_h[i][0] = Ah[buf][tig  ][m+gid]; a_h[i][1] = Ah[buf][tig  ][m+gid+8];
            a_h[i][2] = Ah[buf][tig+4][m+gid]; a_h[i][3] = Ah[buf][tig+4][m+gid+8];
            a_l[i][0] = Al[buf][tig  ][m+gid]; a_l[i][1] = Al[buf][tig  ][m+gid+8];
            a_l[i][2] = Al[buf][tig+4][m+gid]; a_l[i][3] = Al[buf][tig+4][m+gid+8];
        }
        #pragma unroll
        for (int j = 0; j < 4; j++) {
            int n = wn*32 + j*8;
            unsigned b_h[2] = { Bh[buf][tig][n+gid], Bh[buf][tig+4][n+gid] };
            unsigned b_l[2] = { Bl[buf][tig][n+gid], Bl[buf][tig+4][n+gid] };
            #pragma unroll
            for (int i = 0; i < 2; i++) {
                mma16(acc[i][j], a_h[i], b_h);
                mma16(acc[i][j], a_h[i], b_l);
                mma16(acc[i][j], a_l[i], b_h);
            }
        }
    }
    #pragma unroll
    for (int j = 0; j < 4; j++) {
        int n = wn*32 + j*8 + 2*tig;
        #pragma unroll
        for (int i = 0; i < 2; i++) {
            int r = row0 + wm*32 + i*16 + gid;
            atomicAdd(&g_acc[r*HL + n],         acc[i][j][0]);
            atomicAdd(&g_acc[r*HL + n + 1],     acc[i][j][1]);
            atomicAdd(&g_acc[(r+8)*HL + n],     acc[i][j][2]);
            atomicAdd(&g_acc[(r+8)*HL + n + 1], acc[i][j][3]);
        }
    }
}

// ================= epilogue =================
__global__ void k_final(const float* __restrict__ b1, const float* __restrict__ W2,
                        const float* __restrict__ b2, float* __restrict__ out) {
    int g = blockIdx.x*blockDim.x + threadIdx.x;
    if (g >= BG) return;
    float l0 = b2[0], l1 = b2[1];
    #pragma unroll 8
    for (int j = 0; j < HL; j++) {
        float h = fmaxf(g_acc[g*HL + j] + b1[j], 0.0f);
        l0 = fmaf(h, W2[j*2 + 0], l0);
        l1 = fmaf(h, W2[j*2 + 1], l1);
    }
    float m = fmaxf(l0, l1);
    float lse = m + logf(expf(l0 - m) + expf(l1 - m));
    out[g*2 + 0] = l0 - lse;
    out[g*2 + 1] = l1 - lse;
}

// ================= launch =================
extern "C" void kernel_launch(void* const* d_in, const int* in_sizes, int n_in,
                              void* d_out, int out_size) {
    const float* x      = (const float*)d_in[0];
    const float* eattr  = (const float*)d_in[1];
    const float* W1     = (const float*)d_in[2];
    const float* b1     = (const float*)d_in[3];
    const float* W2     = (const float*)d_in[4];
    const float* b2     = (const float*)d_in[5];
    const float* W3     = (const float*)d_in[6];
    const float* b3     = (const float*)d_in[7];
    const float* lin1W  = (const float*)d_in[8];
    const float* lin1b  = (const float*)d_in[9];
    const float* lin2W  = (const float*)d_in[10];
    const float* lin2b  = (const float*)d_in[11];
    const int*   eidx   = (const int*)d_in[12];
    float*       out    = (float*)d_out;

    static int attr_set = 0;
    if (!attr_set) {
        cudaFuncSetAttribute(k_fused, cudaFuncAttributeMaxDynamicSharedMemorySize, SMEMB);
        attr_set = 1;
    }

    k_fused<<<BG, 256, SMEMB>>>(x, eattr, eidx, W1, b1, W2, b2, W3, b3);
    dim3 g1(BG/128, 180);   // split-K: KC=192
    k_lin1<<<g1, 256>>>(lin1W);
    k_final<<<(BG + 255)/256, 256>>>(lin1b, lin2W, lin2b, out);
}

// round 10
// speedup vs baseline: 1.9788x; 1.0165x over previous
#include <cuda_runtime.h>
#include <cuda_bf16.h>
#include <math.h>

#define NN     46080
#define EE     737280
#define BG     512
#define NODES  90
#define EPG    1440
#define HH     128
#define HL     64
#define XCP    192          // xc pairs per node (384 feats / 2)
#define LDA1P  (NODES*XCP)  // 17280 pairs per graph row

#define SA 100              // uint2 stride for A/Ta   (100 % 16 == 4: conflict-free LDS.64)
#define SB 132              // uint2 stride for Hb/W   (132 % 16 == 4)
#define MPF 104             // fp32 stride for F scratch

// smem byte offsets
#define OFF_AA 1024
#define SZ_AA  (48*SA*8)             // 38400
#define OFF_U  (OFF_AA + SZ_AA)      // 39424
#define SZ_U   (64*SA*8)             // 51200 (Ta 64x100; Hb 48x132=50688; F 96x104x4=39936)
#define OFF_W  (OFF_U + SZ_U)        // 90624
#define SZ_WB  (8*SB*8)              // 8448
#define SMEMB  (OFF_W + 2*SZ_WB)     // 107520 bytes (~105 KB) -> 2 CTAs/SM

// ---------------- device scratch ----------------
__device__ uint2 g_xcp[NN*XCP];  // split bf16 pairs {hi,lo}; z viewed [512, 17280]
__device__ float g_acc[BG*HL];   // lin1 split-K accumulator

// ---------------- bf16 split helpers ----------------
__device__ __forceinline__ void f2bf2(float v0, float v1, unsigned &h, unsigned &l) {
    __nv_bfloat16 h0 = __float2bfloat16(v0), h1 = __float2bfloat16(v1);
    float r0 = v0 - __bfloat162float(h0);
    float r1 = v1 - __bfloat162float(h1);
    __nv_bfloat16 l0 = __float2bfloat16(r0), l1 = __float2bfloat16(r1);
    h = ((unsigned)__bfloat16_as_ushort(h1) << 16) | (unsigned)__bfloat16_as_ushort(h0);
    l = ((unsigned)__bfloat16_as_ushort(l1) << 16) | (unsigned)__bfloat16_as_ushort(l0);
}
__device__ __forceinline__ void mma16(float* c, const unsigned* a, const unsigned* b) {
    asm volatile("mma.sync.aligned.m16n8k16.row.col.f32.bf16.bf16.f32 "
        "{%0,%1,%2,%3}, {%4,%5,%6,%7}, {%8,%9}, {%0,%1,%2,%3};"
        : "+f"(c[0]), "+f"(c[1]), "+f"(c[2]), "+f"(c[3])
        : "r"(a[0]), "r"(a[1]), "r"(a[2]), "r"(a[3]), "r"(b[0]), "r"(b[1]));
}
// 3-term split MMA on interleaved fragments
__device__ __forceinline__ void mma3(float* c, const uint2* a, const uint2* b) {
    unsigned ah[4] = {a[0].x, a[1].x, a[2].x, a[3].x};
    unsigned al[4] = {a[0].y, a[1].y, a[2].y, a[3].y};
    unsigned bh[2] = {b[0].x, b[1].x};
    unsigned bl[2] = {b[0].y, b[1].y};
    mma16(c, ah, bh);
    mma16(c, ah, bl);
    mma16(c, al, bh);
}

// ================= fused per-graph 3-layer GCN (mma.sync, M=96, uint2 operands) =================
__global__ void __launch_bounds__(256, 2) k_fused(
    const float* __restrict__ x, const float* __restrict__ eattr,
    const int* __restrict__ ei,
    const float* __restrict__ W1, const float* __restrict__ b1,
    const float* __restrict__ W2, const float* __restrict__ b2,
    const float* __restrict__ W3, const float* __restrict__ b3) {
    extern __shared__ char sm[];
    float* sdeg = (float*)sm;               // 96 @0
    float* sdis = (float*)(sm + 512);       // 96 @512
    uint2* AA = (uint2*)(sm + OFF_AA);      // [k2=48][m<96] stride SA
    uint2* Hb = (uint2*)(sm + OFF_U);       // [k2=48][n=128] stride SB
    uint2* Ta = (uint2*)(sm + OFF_U);       // [k2<=64][m<96] stride SA (aliases Hb)
    float* F  = (float*)(sm + OFF_U);       // [96][MPF] fp32 (prologue only)
    uint2* Wb = (uint2*)(sm + OFF_W);       // [buf][8*SB]

    const int g = blockIdx.x, t = threadIdx.x, lane = t & 31, wid = t >> 5;
    const int wm = wid >> 2, wn = wid & 3;  // 2 x 4 warps; warp tile 48x32
    const int gid = lane >> 2, tig = lane & 3;
    const int eb = g * EPG;

    if (t < HL) g_acc[g*HL + t] = 0.0f;

    // ---- prologue: dense normalized adjacency in F ----
    for (int i = t; i < 96*MPF; i += 256) F[i] = 0.0f;
    if (t < 96) sdeg[t] = 1.0f;
    __syncthreads();
    for (int e = t; e < EPG; e += 256)
        atomicAdd(&sdeg[ei[EE + eb + e] - g*NODES], eattr[eb + e]);
    __syncthreads();
    if (t < 96) sdis[t] = rsqrtf(sdeg[t]);
    __syncthreads();
    for (int e = t; e < EPG; e += 256) {
        int s = ei[eb + e] - g*NODES;
        int d = ei[EE + eb + e] - g*NODES;
        atomicAdd(&F[d*MPF + s], sdis[s] * eattr[eb + e] * sdis[d]);
    }
    if (t < NODES) atomicAdd(&F[t*MPF + t], sdis[t]*sdis[t]);
    __syncthreads();
    // ---- A pairs [k2=src/2][m=dst] ----
    for (int i = t; i < 48*96; i += 256) {
        int k2 = i / 96, m = i - 96*k2;
        unsigned h, l; f2bf2(F[m*MPF + 2*k2], F[m*MPF + 2*k2 + 1], h, l);
        AA[k2*SA + m] = make_uint2(h, l);
    }
    __syncthreads();   // F consumed before Hb0 overwrites U
    // ---- Hb0 = x^T pairs [k2=node/2][n=feat] ----
    for (int i = t; i < 48*128; i += 256) {
        int k2 = i >> 7, n = i & 127;
        int n0 = 2*k2, n1 = n0 + 1;
        float v0 = (n < 90 && n0 < 90) ? x[((long)g*NODES + n0)*90 + n] : 0.0f;
        float v1 = (n < 90 && n1 < 90) ? x[((long)g*NODES + n1)*90 + n] : 0.0f;
        unsigned h, l; f2bf2(v0, v1, h, l);
        Hb[k2*SB + n] = make_uint2(h, l);
    }

    const float* Ws[3]  = {W1, W2, W3};
    const float* bs[3]  = {b1, b2, b3};
    const int    KT2s[3] = {6, 8, 8};
    float acc[3][4][4];

    for (int L = 0; L < 3; L++) {
        __syncthreads();   // Hb ready
        // ======== GEMM1: T[m=96][n=128] = A @ Hb, K=96 ========
        #pragma unroll
        for (int i = 0; i < 3; i++)
            #pragma unroll
            for (int j = 0; j < 4; j++)
                #pragma unroll
                for (int q = 0; q < 4; q++) acc[i][j][q] = 0.0f;
        for (int kt = 0; kt < 6; kt++) {
            int r0 = (kt*8 + tig)*SA, r4 = r0 + 4*SA;
            int s0 = (kt*8 + tig)*SB, s4 = s0 + 4*SB;
            uint2 a[3][4];
            #pragma unroll
            for (int i = 0; i < 3; i++) {
                int m = wm*48 + i*16;
                a[i][0] = AA[r0 + m+gid]; a[i][1] = AA[r0 + m+gid+8];
                a[i][2] = AA[r4 + m+gid]; a[i][3] = AA[r4 + m+gid+8];
            }
            #pragma unroll
            for (int j = 0; j < 4; j++) {
                int n = wn*32 + j*8;
                uint2 b[2] = { Hb[s0 + n+gid], Hb[s4 + n+gid] };
                #pragma unroll
                for (int i = 0; i < 3; i++) mma3(acc[i][j], a[i], b);
            }
        }
        __syncthreads();   // all Hb reads done; U reusable
        // ---- T -> Ta pairs [k2=feat/2][m] ----
        #pragma unroll
        for (int j = 0; j < 4; j++) {
            int k2 = wn*16 + j*4 + tig;
            #pragma unroll
            for (int i = 0; i < 3; i++) {
                int m = wm*48 + i*16 + gid;
                unsigned h, l;
                f2bf2(acc[i][j][0], acc[i][j][1], h, l);
                Ta[k2*SA + m] = make_uint2(h, l);
                f2bf2(acc[i][j][2], acc[i][j][3], h, l);
                Ta[k2*SA + m+8] = make_uint2(h, l);
            }
        }
        // ======== GEMM2: H[m=96][n=128] = Ta @ W (W streamed) ========
        #pragma unroll
        for (int i = 0; i < 3; i++)
            #pragma unroll
            for (int j = 0; j < 4; j++)
                #pragma unroll
                for (int q = 0; q < 4; q++) acc[i][j][q] = 0.0f;
        const float* W = Ws[L];
        const int KT2 = KT2s[L];
        float rW[4][2];
        auto loadw = [&](int kt) {
            #pragma unroll
            for (int q = 0; q < 4; q++) {
                int idx = t*4 + q; int n = idx & 127, k2 = idx >> 7;
                int k = kt*16 + 2*k2;
                rW[q][0] = (L > 0 || k     < 90) ? W[k*HH + n]     : 0.0f;
                rW[q][1] = (L > 0 || k + 1 < 90) ? W[(k+1)*HH + n] : 0.0f;
            }
        };
        loadw(0);
        for (int kt = 0; kt < KT2; kt++) {
            uint2* Wc = Wb + (kt & 1)*(8*SB);
            #pragma unroll
            for (int q = 0; q < 4; q++) {
                int idx = t*4 + q; int n = idx & 127, k2 = idx >> 7;
                unsigned h, l; f2bf2(rW[q][0], rW[q][1], h, l);
                Wc[k2*SB + n] = make_uint2(h, l);
            }
            __syncthreads();   // W tile ready (and, at kt=0, Ta ready)
            if (kt + 1 < KT2) loadw(kt + 1);

            int r0 = (kt*8 + tig)*SA, r4 = r0 + 4*SA;
            int s0 = tig*SB, s4 = s0 + 4*SB;
            uint2 a[3][4];
            #pragma unroll
            for (int i = 0; i < 3; i++) {
                int m = wm*48 + i*16;
                a[i][0] = Ta[r0 + m+gid]; a[i][1] = Ta[r0 + m+gid+8];
                a[i][2] = Ta[r4 + m+gid]; a[i][3] = Ta[r4 + m+gid+8];
            }
            #pragma unroll
            for (int j = 0; j < 4; j++) {
                int n = wn*32 + j*8;
                uint2 b[2] = { Wc[s0 + n+gid], Wc[s4 + n+gid] };
                #pragma unroll
                for (int i = 0; i < 3; i++) mma3(acc[i][j], a[i], b);
            }
            // no trailing sync (double-buffered W; Ta read-only here)
        }
        __syncthreads();   // Ta reads done before Hb-next overwrites U
        // ---- epilogue: relu(+bias) -> g_xcp (split pairs); next Hb via shuffles ----
        const float* bias = bs[L];
        #pragma unroll
        for (int i = 0; i < 3; i++) {
            #pragma unroll
            for (int j = 0; j < 4; j++) {
                int m = wm*48 + i*16 + gid;
                int n = wn*32 + j*8 + 2*tig;
                float b0 = bias[n], b1 = bias[n+1];
                float v0 = fmaxf(acc[i][j][0] + b0, 0.0f);
                float v1 = fmaxf(acc[i][j][1] + b1, 0.0f);
                float v2 = fmaxf(acc[i][j][2] + b0, 0.0f);
                float v3 = fmaxf(acc[i][j][3] + b1, 0.0f);
                int p2 = L*64 + (n >> 1);
                if (m < NODES) {
                    unsigned h, l; f2bf2(v0, v1, h, l);
                    g_xcp[((long)g*NODES + m)*XCP + p2] = make_uint2(h, l);
                }
                if (m + 8 < NODES) {
                    unsigned h, l; f2bf2(v2, v3, h, l);
                    g_xcp[((long)g*NODES + m + 8)*XCP + p2] = make_uint2(h, l);
                }
                if (L < 2) {
                    float p0 = __shfl_down_sync(0xffffffffu, v0, 4);
                    float p1 = __shfl_down_sync(0xffffffffu, v1, 4);
                    float p2f = __shfl_down_sync(0xffffffffu, v2, 4);
                    float p3 = __shfl_down_sync(0xffffffffu, v3, 4);
                    if (!(gid & 1)) {   // even gid owns node pair (m, m+1)
                        int k2 = wm*24 + i*8 + (gid >> 1);
                        unsigned h, l;
                        f2bf2(v0, p0, h, l);  Hb[k2*SB + n]       = make_uint2(h, l);
                        f2bf2(v1, p1, h, l);  Hb[k2*SB + n + 1]   = make_uint2(h, l);
                        f2bf2(v2, p2f, h, l); Hb[(k2+4)*SB + n]   = make_uint2(h, l);
                        f2bf2(v3, p3, h, l);  Hb[(k2+4)*SB + n+1] = make_uint2(h, l);
                    }
                }
            }
        }
    }
}

// ================= lin1: g_acc += z @ lin1_W (A pre-split in g_xcp; no conversions) =================
// tile M=128 N=64, K-chunk 96 pairs (12 kt), grid (4, 180).
__global__ void __launch_bounds__(256, 2) k_lin1(const float* __restrict__ W) {
    __shared__ uint2 As[2][8][SB];
    __shared__ uint2 Bs[2][8][68];
    const int t = threadIdx.x, lane = t & 31, wid = t >> 5;
    const int wm = wid >> 1, wn = wid & 1;
    const int gid = lane >> 2, tig = lane & 3;
    const int row0   = blockIdx.x * 128;
    const int kbase2 = blockIdx.y * 96;      // in pair units
    const int KT = 12;

    const int amj[4] = { (t*4+0) >> 3, (t*4+1) >> 3, (t*4+2) >> 3, (t*4+3) >> 3 };
    const int akj[4] = { (t*4+0) & 7,  (t*4+1) & 7,  (t*4+2) & 7,  (t*4+3) & 7 };
    const int bnj[2] = { (t*2+0) & 63, (t*2+1) & 63 };
    const int bkj[2] = { (t*2+0) >> 6, (t*2+1) >> 6 };

    uint2 rA[4];
    float rB[2][2];
    auto load_tile = [&](int kt) {
        #pragma unroll
        for (int j = 0; j < 4; j++)
            rA[j] = g_xcp[(long)(row0 + amj[j])*LDA1P + kbase2 + kt*8 + akj[j]];
        int k0 = 2*(kbase2 + kt*8);
        #pragma unroll
        for (int j = 0; j < 2; j++) {
            int ka = k0 + 2*bkj[j];
            rB[j][0] = W[ka*HL + bnj[j]];
            rB[j][1] = W[(ka+1)*HL + bnj[j]];
        }
    };

    float acc[2][4][4];
    #pragma unroll
    for (int i = 0; i < 2; i++)
        #pragma unroll
        for (int j = 0; j < 4; j++)
            #pragma unroll
            for (int q = 0; q < 4; q++) acc[i][j][q] = 0.0f;

    load_tile(0);
    for (int kt = 0; kt < KT; kt++) {
        int buf = kt & 1;
        #pragma unroll
        for (int j = 0; j < 4; j++) As[buf][akj[j]][amj[j]] = rA[j];
        #pragma unroll
        for (int j = 0; j < 2; j++) {
            unsigned h, l; f2bf2(rB[j][0], rB[j][1], h, l);
            Bs[buf][bkj[j]][bnj[j]] = make_uint2(h, l);
        }
        __syncthreads();
        if (kt + 1 < KT) load_tile(kt + 1);

        uint2 a[2][4];
        #pragma unroll
        for (int i = 0; i < 2; i++) {
            int m = wm*32 + i*16;
            a[i][0] = As[buf][tig  ][m+gid]; a[i][1] = As[buf][tig  ][m+gid+8];
            a[i][2] = As[buf][tig+4][m+gid]; a[i][3] = As[buf][tig+4][m+gid+8];
        }
        #pragma unroll
        for (int j = 0; j < 4; j++) {
            int n = wn*32 + j*8;
            uint2 b[2] = { Bs[buf][tig][n+gid], Bs[buf][tig+4][n+gid] };
            #pragma unroll
            for (int i = 0; i < 2; i++) mma3(acc[i][j], a[i], b);
        }
    }
    #pragma unroll
    for (int j = 0; j < 4; j++) {
        int n = wn*32 + j*8 + 2*tig;
        #pragma unroll
        for (int i = 0; i < 2; i++) {
            int r = row0 + wm*32 + i*16 + gid;
            atomicAdd(&g_acc[r*HL + n],         acc[i][j][0]);
            atomicAdd(&g_acc[r*HL + n + 1],     acc[i][j][1]);
            atomicAdd(&g_acc[(r+8)*HL + n],     acc[i][j][2]);
            atomicAdd(&g_acc[(r+8)*HL + n + 1], acc[i][j][3]);
        }
    }
}

// ================= epilogue =================
__global__ void k_final(const float* __restrict__ b1, const float* __restrict__ W2,
                        const float* __restrict__ b2, float* __restrict__ out) {
    int g = blockIdx.x*blockDim.x + threadIdx.x;
    if (g >= BG) return;
    float l0 = b2[0], l1 = b2[1];
    #pragma unroll 8
    for (int j = 0; j < HL; j++) {
        float h = fmaxf(g_acc[g*HL + j] + b1[j], 0.0f);
        l0 = fmaf(h, W2[j*2 + 0], l0);
        l1 = fmaf(h, W2[j*2 + 1], l1);
    }
    float m = fmaxf(l0, l1);
    float lse = m + logf(expf(l0 - m) + expf(l1 - m));
    out[g*2 + 0] = l0 - lse;
    out[g*2 + 1] = l1 - lse;
}

// ================= launch =================
extern "C" void kernel_launch(void* const* d_in, const int* in_sizes, int n_in,
                              void* d_out, int out_size) {
    const float* x      = (const float*)d_in[0];
    const float* eattr  = (const float*)d_in[1];
    const float* W1     = (const float*)d_in[2];
    const float* b1     = (const float*)d_in[3];
    const float* W2     = (const float*)d_in[4];
    const float* b2     = (const float*)d_in[5];
    const float* W3     = (const float*)d_in[6];
    const float* b3     = (const float*)d_in[7];
    const float* lin1W  = (const float*)d_in[8];
    const float* lin1b  = (const float*)d_in[9];
    const float* lin2W  = (const float*)d_in[10];
    const float* lin2b  = (const float*)d_in[11];
    const int*   eidx   = (const int*)d_in[12];
    float*       out    = (float*)d_out;

    static int attr_set = 0;
    if (!attr_set) {
        cudaFuncSetAttribute(k_fused, cudaFuncAttributeMaxDynamicSharedMemorySize, SMEMB);
        attr_set = 1;
    }

    k_fused<<<BG, 256, SMEMB>>>(x, eattr, eidx, W1, b1, W2, b2, W3, b3);
    dim3 g1(BG/128, 180);
    k_lin1<<<g1, 256>>>(lin1W);
    k_final<<<(BG + 255)/256, 256>>>(lin1b, lin2W, lin2b, out);
}

// round 11
// speedup vs baseline: 2.1469x; 1.0850x over previous
#include <cuda_runtime.h>
#include <cuda_bf16.h>
#include <math.h>

#define NN     46080
#define EE     737280
#define BG     512
#define NODES  90
#define EPG    1440
#define HH     128
#define HL     64
#define XCP    192          // xc pairs per node (384 feats / 2)
#define LDA1P  (NODES*XCP)  // 17280 pairs per graph row

#define MP 104              // m-stride (u32) for A/Ta  (104 % 32 == 8: conflict-free)
#define NP 136              // n-stride (u32) for Hb/W  (136 % 32 == 8)
#define SB 132              // uint2 stride in k_lin1 As

// k_fused smem byte offsets (R9 layout)
#define OFF_A0  1024
#define SZ_A    (48*MP*4)            // 19968
#define OFF_A1  (OFF_A0 + SZ_A)
#define OFF_U   (OFF_A1 + SZ_A)      // 40960
#define SZ_U    (2*64*MP*4)          // 53248
#define OFF_W   (OFF_U + SZ_U)       // 94208
#define SZ_WB   (8*NP*4)             // 4352
#define SMEMB   (OFF_W + 4*SZ_WB)    // 111616 bytes -> 2 CTAs/SM

// ---------------- device scratch ----------------
__device__ uint2 g_xcp[NN*XCP];  // split bf16 pairs {hi,lo}; z viewed [512, 17280]
__device__ float g_acc[BG*HL];   // lin1 split-K accumulator

// ---------------- bf16 split helpers ----------------
__device__ __forceinline__ void f2bf2(float v0, float v1, unsigned &h, unsigned &l) {
    __nv_bfloat16 h0 = __float2bfloat16(v0), h1 = __float2bfloat16(v1);
    float r0 = v0 - __bfloat162float(h0);
    float r1 = v1 - __bfloat162float(h1);
    __nv_bfloat16 l0 = __float2bfloat16(r0), l1 = __float2bfloat16(r1);
    h = ((unsigned)__bfloat16_as_ushort(h1) << 16) | (unsigned)__bfloat16_as_ushort(h0);
    l = ((unsigned)__bfloat16_as_ushort(l1) << 16) | (unsigned)__bfloat16_as_ushort(l0);
}
__device__ __forceinline__ void mma16(float* c, const unsigned* a, const unsigned* b) {
    asm volatile("mma.sync.aligned.m16n8k16.row.col.f32.bf16.bf16.f32 "
        "{%0,%1,%2,%3}, {%4,%5,%6,%7}, {%8,%9}, {%0,%1,%2,%3};"
        : "+f"(c[0]), "+f"(c[1]), "+f"(c[2]), "+f"(c[3])
        : "r"(a[0]), "r"(a[1]), "r"(a[2]), "r"(a[3]), "r"(b[0]), "r"(b[1]));
}
__device__ __forceinline__ void mma3u(float* c, const uint2* a, const uint2* b) {
    unsigned ah[4] = {a[0].x, a[1].x, a[2].x, a[3].x};
    unsigned al[4] = {a[0].y, a[1].y, a[2].y, a[3].y};
    unsigned bh[2] = {b[0].x, b[1].x};
    unsigned bl[2] = {b[0].y, b[1].y};
    mma16(c, ah, bh);
    mma16(c, ah, bl);
    mma16(c, al, bh);
}

// ================= fused per-graph 3-layer GCN (R9 layout; epilogue -> g_xcp) =================
__global__ void __launch_bounds__(256, 2) k_fused(
    const float* __restrict__ x, const float* __restrict__ eattr,
    const int* __restrict__ ei,
    const float* __restrict__ W1, const float* __restrict__ b1,
    const float* __restrict__ W2, const float* __restrict__ b2,
    const float* __restrict__ W3, const float* __restrict__ b3) {
    extern __shared__ char sm[];
    float*    sdeg = (float*)sm;               // 96 @0
    float*    sdis = (float*)(sm + 512);       // 96 @512
    unsigned* Aah  = (unsigned*)(sm + OFF_A0); // [k2=48][m<=96] stride MP
    unsigned* Aal  = (unsigned*)(sm + OFF_A1);
    unsigned* HbH  = (unsigned*)(sm + OFF_U);                  // [k2=48][n=128] stride NP
    unsigned* HbL  = (unsigned*)(sm + OFF_U + 48*NP*4);
    unsigned* TaH  = (unsigned*)(sm + OFF_U);                  // [k2=64][m<=96] stride MP
    unsigned* TaL  = (unsigned*)(sm + OFF_U + 64*MP*4);
    float*    F    = (float*)(sm + OFF_U);                     // [96][MP] fp32 (prologue only)
    unsigned* Wb   = (unsigned*)(sm + OFF_W);                  // [buf][hl][8*NP]

    const int g = blockIdx.x, t = threadIdx.x, lane = t & 31, wid = t >> 5;
    const int wm = wid >> 2, wn = wid & 3;      // 2 x 4 warps; warp tile 48x32
    const int gid = lane >> 2, tig = lane & 3;
    const int eb = g * EPG;

    if (t < HL) g_acc[g*HL + t] = 0.0f;

    // ---- prologue: dense normalized adjacency in F (aliases U) ----
    for (int i = t; i < 96*MP; i += 256) F[i] = 0.0f;
    if (t < 96) sdeg[t] = 1.0f;
    __syncthreads();
    for (int e = t; e < EPG; e += 256)
        atomicAdd(&sdeg[ei[EE + eb + e] - g*NODES], eattr[eb + e]);
    __syncthreads();
    if (t < 96) sdis[t] = rsqrtf(sdeg[t]);
    __syncthreads();
    for (int e = t; e < EPG; e += 256) {
        int s = ei[eb + e] - g*NODES;
        int d = ei[EE + eb + e] - g*NODES;
        atomicAdd(&F[d*MP + s], sdis[s] * eattr[eb + e] * sdis[d]);
    }
    if (t < NODES) atomicAdd(&F[t*MP + t], sdis[t]*sdis[t]);
    __syncthreads();
    // ---- A pairs [k2=src/2][m=dst] ----
    for (int i = t; i < 48*96; i += 256) {
        int k2 = i / 96, m = i - 96*k2;
        unsigned h, l; f2bf2(F[m*MP + 2*k2], F[m*MP + 2*k2 + 1], h, l);
        Aah[k2*MP + m] = h; Aal[k2*MP + m] = l;
    }
    __syncthreads();   // F fully consumed before Hb0 overwrites U
    // ---- Hb0 = x^T pairs [k2=node/2][n=feat] ----
    for (int i = t; i < 48*128; i += 256) {
        int k2 = i >> 7, n = i & 127;
        int n0 = 2*k2, n1 = n0 + 1;
        float v0 = (n < 90 && n0 < 90) ? x[((long)g*NODES + n0)*90 + n] : 0.0f;
        float v1 = (n < 90 && n1 < 90) ? x[((long)g*NODES + n1)*90 + n] : 0.0f;
        unsigned h, l; f2bf2(v0, v1, h, l);
        HbH[k2*NP + n] = h; HbL[k2*NP + n] = l;
    }

    const float* Ws[3]  = {W1, W2, W3};
    const float* bs[3]  = {b1, b2, b3};
    const int    KT2s[3] = {6, 8, 8};
    float acc[3][4][4];

    for (int L = 0; L < 3; L++) {
        __syncthreads();   // Hb ready
        // ======== GEMM1: T[m=96][n=128] = A @ Hb, K=96 ========
        #pragma unroll
        for (int i = 0; i < 3; i++)
            #pragma unroll
            for (int j = 0; j < 4; j++)
                #pragma unroll
                for (int q = 0; q < 4; q++) acc[i][j][q] = 0.0f;
        for (int kt = 0; kt < 6; kt++) {
            int r0 = (kt*8 + tig)*MP, r4 = r0 + 4*MP;
            int s0 = (kt*8 + tig)*NP, s4 = s0 + 4*NP;
            unsigned a_h[3][4], a_l[3][4];
            #pragma unroll
            for (int i = 0; i < 3; i++) {
                int m = wm*48 + i*16;
                a_h[i][0] = Aah[r0 + m+gid]; a_h[i][1] = Aah[r0 + m+gid+8];
                a_h[i][2] = Aah[r4 + m+gid]; a_h[i][3] = Aah[r4 + m+gid+8];
                a_l[i][0] = Aal[r0 + m+gid]; a_l[i][1] = Aal[r0 + m+gid+8];
                a_l[i][2] = Aal[r4 + m+gid]; a_l[i][3] = Aal[r4 + m+gid+8];
            }
            #pragma unroll
            for (int j = 0; j < 4; j++) {
                int n = wn*32 + j*8;
                unsigned b_h[2] = { HbH[s0 + n+gid], HbH[s4 + n+gid] };
                unsigned b_l[2] = { HbL[s0 + n+gid], HbL[s4 + n+gid] };
                #pragma unroll
                for (int i = 0; i < 3; i++) {
                    mma16(acc[i][j], a_h[i], b_h);
                    mma16(acc[i][j], a_h[i], b_l);
                    mma16(acc[i][j], a_l[i], b_h);
                }
            }
        }
        __syncthreads();   // all Hb reads done; U reusable
        // ---- T -> Ta pairs [k2=feat/2][m] ----
        #pragma unroll
        for (int j = 0; j < 4; j++) {
            int k2 = wn*16 + j*4 + tig;
            #pragma unroll
            for (int i = 0; i < 3; i++) {
                int m = wm*48 + i*16 + gid;
                unsigned h, l;
                f2bf2(acc[i][j][0], acc[i][j][1], h, l);
                TaH[k2*MP + m] = h; TaL[k2*MP + m] = l;
                f2bf2(acc[i][j][2], acc[i][j][3], h, l);
                TaH[k2*MP + m+8] = h; TaL[k2*MP + m+8] = l;
            }
        }
        // ======== GEMM2: H[m=96][n=128] = Ta @ W (W streamed) ========
        #pragma unroll
        for (int i = 0; i < 3; i++)
            #pragma unroll
            for (int j = 0; j < 4; j++)
                #pragma unroll
                for (int q = 0; q < 4; q++) acc[i][j][q] = 0.0f;
        const float* W = Ws[L];
        const int KT2 = KT2s[L];
        float rW[4][2];
        auto loadw = [&](int kt) {
            #pragma unroll
            for (int q = 0; q < 4; q++) {
                int idx = t*4 + q; int n = idx & 127, k2 = idx >> 7;
                int k = kt*16 + 2*k2;
                rW[q][0] = (L > 0 || k     < 90) ? W[k*HH + n]     : 0.0f;
                rW[q][1] = (L > 0 || k + 1 < 90) ? W[(k+1)*HH + n] : 0.0f;
            }
        };
        loadw(0);
        for (int kt = 0; kt < KT2; kt++) {
            int buf = kt & 1;
            unsigned* Wh = Wb + buf*(2*8*NP);
            unsigned* Wl = Wh + 8*NP;
            #pragma unroll
            for (int q = 0; q < 4; q++) {
                int idx = t*4 + q; int n = idx & 127, k2 = idx >> 7;
                unsigned h, l; f2bf2(rW[q][0], rW[q][1], h, l);
                Wh[k2*NP + n] = h; Wl[k2*NP + n] = l;
            }
            __syncthreads();   // W tile ready (and, at kt=0, Ta ready)
            if (kt + 1 < KT2) loadw(kt + 1);

            int r0 = (kt*8 + tig)*MP, r4 = r0 + 4*MP;
            int s0 = tig*NP, s4 = s0 + 4*NP;
            unsigned a_h[3][4], a_l[3][4];
            #pragma unroll
            for (int i = 0; i < 3; i++) {
                int m = wm*48 + i*16;
                a_h[i][0] = TaH[r0 + m+gid]; a_h[i][1] = TaH[r0 + m+gid+8];
                a_h[i][2] = TaH[r4 + m+gid]; a_h[i][3] = TaH[r4 + m+gid+8];
                a_l[i][0] = TaL[r0 + m+gid]; a_l[i][1] = TaL[r0 + m+gid+8];
                a_l[i][2] = TaL[r4 + m+gid]; a_l[i][3] = TaL[r4 + m+gid+8];
            }
            #pragma unroll
            for (int j = 0; j < 4; j++) {
                int n = wn*32 + j*8;
                unsigned b_h[2] = { Wh[s0 + n+gid], Wh[s4 + n+gid] };
                unsigned b_l[2] = { Wl[s0 + n+gid], Wl[s4 + n+gid] };
                #pragma unroll
                for (int i = 0; i < 3; i++) {
                    mma16(acc[i][j], a_h[i], b_h);
                    mma16(acc[i][j], a_h[i], b_l);
                    mma16(acc[i][j], a_l[i], b_h);
                }
            }
            // no trailing sync (double-buffered W; Ta read-only here)
        }
        __syncthreads();   // Ta reads done before Hb-next overwrites U
        // ---- epilogue: relu(+bias) -> g_xcp (split pairs); next Hb via shuffles ----
        const float* bias = bs[L];
        #pragma unroll
        for (int i = 0; i < 3; i++) {
            #pragma unroll
            for (int j = 0; j < 4; j++) {
                int m = wm*48 + i*16 + gid;
                int n = wn*32 + j*8 + 2*tig;
                float b0 = bias[n], b1 = bias[n+1];
                float v0 = fmaxf(acc[i][j][0] + b0, 0.0f);
                float v1 = fmaxf(acc[i][j][1] + b1, 0.0f);
                float v2 = fmaxf(acc[i][j][2] + b0, 0.0f);
                float v3 = fmaxf(acc[i][j][3] + b1, 0.0f);
                int p2 = L*64 + (n >> 1);
                if (m < NODES) {
                    unsigned h, l; f2bf2(v0, v1, h, l);
                    g_xcp[((long)g*NODES + m)*XCP + p2] = make_uint2(h, l);
                }
                if (m + 8 < NODES) {
                    unsigned h, l; f2bf2(v2, v3, h, l);
                    g_xcp[((long)g*NODES + m + 8)*XCP + p2] = make_uint2(h, l);
                }
                if (L < 2) {
                    float q0 = __shfl_down_sync(0xffffffffu, v0, 4);
                    float q1 = __shfl_down_sync(0xffffffffu, v1, 4);
                    float q2 = __shfl_down_sync(0xffffffffu, v2, 4);
                    float q3 = __shfl_down_sync(0xffffffffu, v3, 4);
                    if (!(gid & 1)) {   // even gid owns node pair (m, m+1)
                        int k2 = wm*24 + i*8 + (gid >> 1);
                        unsigned h, l;
                        f2bf2(v0, q0, h, l); HbH[k2*NP + n]       = h; HbL[k2*NP + n]       = l;
                        f2bf2(v1, q1, h, l); HbH[k2*NP + n + 1]   = h; HbL[k2*NP + n + 1]   = l;
                        f2bf2(v2, q2, h, l); HbH[(k2+4)*NP + n]   = h; HbL[(k2+4)*NP + n]   = l;
                        f2bf2(v3, q3, h, l); HbH[(k2+4)*NP + n+1] = h; HbL[(k2+4)*NP + n+1] = l;
                    }
                }
            }
        }
    }
}

// ================= lin1 (R10 version: pre-split A, no conversions) =================
__global__ void __launch_bounds__(256, 2) k_lin1(const float* __restrict__ W) {
    __shared__ uint2 As[2][8][SB];
    __shared__ uint2 Bs[2][8][68];
    const int t = threadIdx.x, lane = t & 31, wid = t >> 5;
    const int wm = wid >> 1, wn = wid & 1;
    const int gid = lane >> 2, tig = lane & 3;
    const int row0   = blockIdx.x * 128;
    const int kbase2 = blockIdx.y * 96;      // in pair units
    const int KT = 12;

    const int amj[4] = { (t*4+0) >> 3, (t*4+1) >> 3, (t*4+2) >> 3, (t*4+3) >> 3 };
    const int akj[4] = { (t*4+0) & 7,  (t*4+1) & 7,  (t*4+2) & 7,  (t*4+3) & 7 };
    const int bnj[2] = { (t*2+0) & 63, (t*2+1) & 63 };
    const int bkj[2] = { (t*2+0) >> 6, (t*2+1) >> 6 };

    uint2 rA[4];
    float rB[2][2];
    auto load_tile = [&](int kt) {
        #pragma unroll
        for (int j = 0; j < 4; j++)
            rA[j] = g_xcp[(long)(row0 + amj[j])*LDA1P + kbase2 + kt*8 + akj[j]];
        int k0 = 2*(kbase2 + kt*8);
        #pragma unroll
        for (int j = 0; j < 2; j++) {
            int ka = k0 + 2*bkj[j];
            rB[j][0] = W[ka*HL + bnj[j]];
            rB[j][1] = W[(ka+1)*HL + bnj[j]];
        }
    };

    float acc[2][4][4];
    #pragma unroll
    for (int i = 0; i < 2; i++)
        #pragma unroll
        for (int j = 0; j < 4; j++)
            #pragma unroll
            for (int q = 0; q < 4; q++) acc[i][j][q] = 0.0f;

    load_tile(0);
    for (int kt = 0; kt < KT; kt++) {
        int buf = kt & 1;
        #pragma unroll
        for (int j = 0; j < 4; j++) As[buf][akj[j]][amj[j]] = rA[j];
        #pragma unroll
        for (int j = 0; j < 2; j++) {
            unsigned h, l; f2bf2(rB[j][0], rB[j][1], h, l);
            Bs[buf][bkj[j]][bnj[j]] = make_uint2(h, l);
        }
        __syncthreads();
        if (kt + 1 < KT) load_tile(kt + 1);

        uint2 a[2][4];
        #pragma unroll
        for (int i = 0; i < 2; i++) {
            int m = wm*32 + i*16;
            a[i][0] = As[buf][tig  ][m+gid]; a[i][1] = As[buf][tig  ][m+gid+8];
            a[i][2] = As[buf][tig+4][m+gid]; a[i][3] = As[buf][tig+4][m+gid+8];
        }
        #pragma unroll
        for (int j = 0; j < 4; j++) {
            int n = wn*32 + j*8;
            uint2 b[2] = { Bs[buf][tig][n+gid], Bs[buf][tig+4][n+gid] };
            #pragma unroll
            for (int i = 0; i < 2; i++) mma3u(acc[i][j], a[i], b);
        }
    }
    #pragma unroll
    for (int j = 0; j < 4; j++) {
        int n = wn*32 + j*8 + 2*tig;
        #pragma unroll
        for (int i = 0; i < 2; i++) {
            int r = row0 + wm*32 + i*16 + gid;
            atomicAdd(&g_acc[r*HL + n],         acc[i][j][0]);
            atomicAdd(&g_acc[r*HL + n + 1],     acc[i][j][1]);
            atomicAdd(&g_acc[(r+8)*HL + n],     acc[i][j][2]);
            atomicAdd(&g_acc[(r+8)*HL + n + 1], acc[i][j][3]);
        }
    }
}

// ================= epilogue =================
__global__ void k_final(const float* __restrict__ b1, const float* __restrict__ W2,
                        const float* __restrict__ b2, float* __restrict__ out) {
    int g = blockIdx.x*blockDim.x + threadIdx.x;
    if (g >= BG) return;
    float l0 = b2[0], l1 = b2[1];
    #pragma unroll 8
    for (int j = 0; j < HL; j++) {
        float h = fmaxf(g_acc[g*HL + j] + b1[j], 0.0f);
        l0 = fmaf(h, W2[j*2 + 0], l0);
        l1 = fmaf(h, W2[j*2 + 1], l1);
    }
    float m = fmaxf(l0, l1);
    float lse = m + logf(expf(l0 - m) + expf(l1 - m));
    out[g*2 + 0] = l0 - lse;
    out[g*2 + 1] = l1 - lse;
}

// ================= launch =================
extern "C" void kernel_launch(void* const* d_in, const int* in_sizes, int n_in,
                              void* d_out, int out_size) {
    const float* x      = (const float*)d_in[0];
    const float* eattr  = (const float*)d_in[1];
    const float* W1     = (const float*)d_in[2];
    const float* b1     = (const float*)d_in[3];
    const float* W2     = (const float*)d_in[4];
    const float* b2     = (const float*)d_in[5];
    const float* W3     = (const float*)d_in[6];
    const float* b3     = (const float*)d_in[7];
    const float* lin1W  = (const float*)d_in[8];
    const float* lin1b  = (const float*)d_in[9];
    const float* lin2W  = (const float*)d_in[10];
    const float* lin2b  = (const float*)d_in[11];
    const int*   eidx   = (const int*)d_in[12];
    float*       out    = (float*)d_out;

    static int attr_set = 0;
    if (!attr_set) {
        cudaFuncSetAttribute(k_fused, cudaFuncAttributeMaxDynamicSharedMemorySize, SMEMB);
        attr_set = 1;
    }

    k_fused<<<BG, 256, SMEMB>>>(x, eattr, eidx, W1, b1, W2, b2, W3, b3);
    dim3 g1(BG/128, 180);
    k_lin1<<<g1, 256>>>(lin1W);
    k_final<<<(BG + 255)/256, 256>>>(lin1b, lin2W, lin2b, out);
}

// round 12
// speedup vs baseline: 2.5055x; 1.1670x over previous
#include <cuda_runtime.h>
#include <cuda_bf16.h>
#include <math.h>

#define NN     46080
#define EE     737280
#define BG     512
#define NODES  90
#define EPG    1440
#define HH     128
#define HL     64
#define XCP    192          // xc pairs per node (384 feats / 2)
#define LDA1P  (NODES*XCP)  // 17280 pairs per graph row

#define MP 104              // m-stride (u32) for A/Ta  (104 % 32 == 8: conflict-free)
#define NP 136              // n-stride (u32) for Hb/W  (136 % 32 == 8)
#define SBL 132             // uint2 stride in k_lin1 As

// k_fused smem byte offsets (R9 layout)
#define OFF_A0  1024
#define SZ_A    (48*MP*4)            // 19968
#define OFF_A1  (OFF_A0 + SZ_A)
#define OFF_U   (OFF_A1 + SZ_A)      // 40960
#define SZ_U    (2*64*MP*4)          // 53248
#define OFF_W   (OFF_U + SZ_U)       // 94208
#define SZ_WB   (8*NP*4)             // 4352
#define SMEMB   (OFF_W + 4*SZ_WB)    // 111616 bytes -> 2 CTAs/SM

// ---------------- device scratch ----------------
__device__ uint2    g_xcp[NN*XCP];      // split bf16 pairs {hi,lo}
__device__ float    g_acc[BG*HL];       // lin1 split-K accumulator
__device__ unsigned g_wh[3*64*128];     // conv W hi plane [L][k2][n], zero-padded
__device__ unsigned g_wl[3*64*128];     // conv W lo plane
__device__ uint2    g_l1w[17280*64];    // lin1 W pairs [k2][n]

// ---------------- bf16 split helpers ----------------
__device__ __forceinline__ void f2bf2(float v0, float v1, unsigned &h, unsigned &l) {
    __nv_bfloat16 h0 = __float2bfloat16(v0), h1 = __float2bfloat16(v1);
    float r0 = v0 - __bfloat162float(h0);
    float r1 = v1 - __bfloat162float(h1);
    __nv_bfloat16 l0 = __float2bfloat16(r0), l1 = __float2bfloat16(r1);
    h = ((unsigned)__bfloat16_as_ushort(h1) << 16) | (unsigned)__bfloat16_as_ushort(h0);
    l = ((unsigned)__bfloat16_as_ushort(l1) << 16) | (unsigned)__bfloat16_as_ushort(l0);
}
__device__ __forceinline__ void mma16(float* c, const unsigned* a, const unsigned* b) {
    asm volatile("mma.sync.aligned.m16n8k16.row.col.f32.bf16.bf16.f32 "
        "{%0,%1,%2,%3}, {%4,%5,%6,%7}, {%8,%9}, {%0,%1,%2,%3};"
        : "+f"(c[0]), "+f"(c[1]), "+f"(c[2]), "+f"(c[3])
        : "r"(a[0]), "r"(a[1]), "r"(a[2]), "r"(a[3]), "r"(b[0]), "r"(b[1]));
}
__device__ __forceinline__ void mma3u(float* c, const uint2* a, const uint2* b) {
    unsigned ah[4] = {a[0].x, a[1].x, a[2].x, a[3].x};
    unsigned al[4] = {a[0].y, a[1].y, a[2].y, a[3].y};
    unsigned bh[2] = {b[0].x, b[1].x};
    unsigned bl[2] = {b[0].y, b[1].y};
    mma16(c, ah, bh);
    mma16(c, ah, bl);
    mma16(c, al, bh);
}

// ================= weight pre-split =================
__global__ void k_prew(const float* __restrict__ W1, const float* __restrict__ W2,
                       const float* __restrict__ W3, const float* __restrict__ l1w) {
    int i = blockIdx.x*blockDim.x + threadIdx.x;
    if (i < 3*64*128) {
        int L = i >> 13;            // / 8192
        int r = i & 8191;
        int k2 = r >> 7, n = r & 127;
        const float* W = (L == 0) ? W1 : (L == 1) ? W2 : W3;
        int KW = (L == 0) ? 90 : 128;
        int k = 2*k2;
        float v0 = (k     < KW) ? W[k*HH + n]     : 0.0f;
        float v1 = (k + 1 < KW) ? W[(k+1)*HH + n] : 0.0f;
        unsigned h, l; f2bf2(v0, v1, h, l);
        g_wh[i] = h; g_wl[i] = l;
    } else {
        int j = i - 3*64*128;
        if (j < 17280*64) {
            int k2 = j >> 6, n = j & 63;
            unsigned h, l;
            f2bf2(l1w[(2*k2)*HL + n], l1w[(2*k2+1)*HL + n], h, l);
            g_l1w[j] = make_uint2(h, l);
        }
    }
}

// ================= fused per-graph 3-layer GCN =================
__global__ void __launch_bounds__(256, 2) k_fused(
    const float* __restrict__ x, const float* __restrict__ eattr,
    const int* __restrict__ ei,
    const float* __restrict__ b1, const float* __restrict__ b2,
    const float* __restrict__ b3) {
    extern __shared__ char sm[];
    float*    sdeg = (float*)sm;               // 96 @0
    float*    sdis = (float*)(sm + 512);       // 96 @512
    unsigned* Aah  = (unsigned*)(sm + OFF_A0); // [k2=48][m<=96] stride MP
    unsigned* Aal  = (unsigned*)(sm + OFF_A1);
    unsigned* HbH  = (unsigned*)(sm + OFF_U);                  // [k2=48][n=128] stride NP
    unsigned* HbL  = (unsigned*)(sm + OFF_U + 48*NP*4);
    unsigned* TaH  = (unsigned*)(sm + OFF_U);                  // [k2=64][m<=96] stride MP
    unsigned* TaL  = (unsigned*)(sm + OFF_U + 64*MP*4);
    float*    F    = (float*)(sm + OFF_U);                     // [96][MP] fp32 (prologue only)
    unsigned* Wb   = (unsigned*)(sm + OFF_W);                  // [buf][hl][8*NP]

    const int g = blockIdx.x, t = threadIdx.x, lane = t & 31, wid = t >> 5;
    const int wm = wid >> 2, wn = wid & 3;      // 2 x 4 warps; warp tile 48x32
    const int gid = lane >> 2, tig = lane & 3;
    const int eb = g * EPG;

    if (t < HL) g_acc[g*HL + t] = 0.0f;

    // ---- prologue: dense normalized adjacency in F (aliases U) ----
    for (int i = t; i < 96*MP; i += 256) F[i] = 0.0f;
    if (t < 96) sdeg[t] = 1.0f;
    __syncthreads();
    for (int e = t; e < EPG; e += 256)
        atomicAdd(&sdeg[ei[EE + eb + e] - g*NODES], eattr[eb + e]);
    __syncthreads();
    if (t < 96) sdis[t] = rsqrtf(sdeg[t]);
    __syncthreads();
    for (int e = t; e < EPG; e += 256) {
        int s = ei[eb + e] - g*NODES;
        int d = ei[EE + eb + e] - g*NODES;
        atomicAdd(&F[d*MP + s], sdis[s] * eattr[eb + e] * sdis[d]);
    }
    if (t < NODES) atomicAdd(&F[t*MP + t], sdis[t]*sdis[t]);
    __syncthreads();
    // ---- A pairs [k2=src/2][m=dst] ----
    for (int i = t; i < 48*96; i += 256) {
        int k2 = i / 96, m = i - 96*k2;
        unsigned h, l; f2bf2(F[m*MP + 2*k2], F[m*MP + 2*k2 + 1], h, l);
        Aah[k2*MP + m] = h; Aal[k2*MP + m] = l;
    }
    __syncthreads();   // F fully consumed before Hb0 overwrites U
    // ---- Hb0 = x^T pairs [k2=node/2][n=feat] ----
    for (int i = t; i < 48*128; i += 256) {
        int k2 = i >> 7, n = i & 127;
        int n0 = 2*k2, n1 = n0 + 1;
        float v0 = (n < 90 && n0 < 90) ? x[((long)g*NODES + n0)*90 + n] : 0.0f;
        float v1 = (n < 90 && n1 < 90) ? x[((long)g*NODES + n1)*90 + n] : 0.0f;
        unsigned h, l; f2bf2(v0, v1, h, l);
        HbH[k2*NP + n] = h; HbL[k2*NP + n] = l;
    }

    const float* bs[3]  = {b1, b2, b3};
    const int    KT2s[3] = {6, 8, 8};
    const int k2w = t >> 5;          // W-load row (0..7)
    const int n0w = (t*4) & 127;     // W-load col base
    float acc[3][4][4];

    for (int L = 0; L < 3; L++) {
        __syncthreads();   // Hb ready
        // ======== GEMM1: T[m=96][n=128] = A @ Hb, K=96 ========
        #pragma unroll
        for (int i = 0; i < 3; i++)
            #pragma unroll
            for (int j = 0; j < 4; j++)
                #pragma unroll
                for (int q = 0; q < 4; q++) acc[i][j][q] = 0.0f;
        for (int kt = 0; kt < 6; kt++) {
            int r0 = (kt*8 + tig)*MP, r4 = r0 + 4*MP;
            int s0 = (kt*8 + tig)*NP, s4 = s0 + 4*NP;
            unsigned a_h[3][4], a_l[3][4];
            #pragma unroll
            for (int i = 0; i < 3; i++) {
                int m = wm*48 + i*16;
                a_h[i][0] = Aah[r0 + m+gid]; a_h[i][1] = Aah[r0 + m+gid+8];
                a_h[i][2] = Aah[r4 + m+gid]; a_h[i][3] = Aah[r4 + m+gid+8];
                a_l[i][0] = Aal[r0 + m+gid]; a_l[i][1] = Aal[r0 + m+gid+8];
                a_l[i][2] = Aal[r4 + m+gid]; a_l[i][3] = Aal[r4 + m+gid+8];
            }
            #pragma unroll
            for (int j = 0; j < 4; j++) {
                int n = wn*32 + j*8;
                unsigned b_h[2] = { HbH[s0 + n+gid], HbH[s4 + n+gid] };
                unsigned b_l[2] = { HbL[s0 + n+gid], HbL[s4 + n+gid] };
                #pragma unroll
                for (int i = 0; i < 3; i++) {
                    mma16(acc[i][j], a_h[i], b_h);
                    mma16(acc[i][j], a_h[i], b_l);
                    mma16(acc[i][j], a_l[i], b_h);
                }
            }
        }
        __syncthreads();   // all Hb reads done; U reusable
        // ---- T -> Ta pairs [k2=feat/2][m] ----
        #pragma unroll
        for (int j = 0; j < 4; j++) {
            int k2 = wn*16 + j*4 + tig;
            #pragma unroll
            for (int i = 0; i < 3; i++) {
                int m = wm*48 + i*16 + gid;
                unsigned h, l;
                f2bf2(acc[i][j][0], acc[i][j][1], h, l);
                TaH[k2*MP + m] = h; TaL[k2*MP + m] = l;
                f2bf2(acc[i][j][2], acc[i][j][3], h, l);
                TaH[k2*MP + m+8] = h; TaL[k2*MP + m+8] = l;
            }
        }
        // ======== GEMM2: H[m=96][n=128] = Ta @ W (pre-split W streamed) ========
        #pragma unroll
        for (int i = 0; i < 3; i++)
            #pragma unroll
            for (int j = 0; j < 4; j++)
                #pragma unroll
                for (int q = 0; q < 4; q++) acc[i][j][q] = 0.0f;
        const unsigned* WhP = g_wh + L*8192;
        const unsigned* WlP = g_wl + L*8192;
        const int KT2 = KT2s[L];
        uint4 rWh, rWl;
        auto loadw = [&](int kt) {
            rWh = *(const uint4*)&WhP[(kt*8 + k2w)*128 + n0w];
            rWl = *(const uint4*)&WlP[(kt*8 + k2w)*128 + n0w];
        };
        loadw(0);
        for (int kt = 0; kt < KT2; kt++) {
            int buf = kt & 1;
            unsigned* Wh = Wb + buf*(2*8*NP);
            unsigned* Wl = Wh + 8*NP;
            *(uint4*)&Wh[k2w*NP + n0w] = rWh;
            *(uint4*)&Wl[k2w*NP + n0w] = rWl;
            __syncthreads();   // W tile ready (and, at kt=0, Ta ready)
            if (kt + 1 < KT2) loadw(kt + 1);

            int r0 = (kt*8 + tig)*MP, r4 = r0 + 4*MP;
            int s0 = tig*NP, s4 = s0 + 4*NP;
            unsigned a_h[3][4], a_l[3][4];
            #pragma unroll
            for (int i = 0; i < 3; i++) {
                int m = wm*48 + i*16;
                a_h[i][0] = TaH[r0 + m+gid]; a_h[i][1] = TaH[r0 + m+gid+8];
                a_h[i][2] = TaH[r4 + m+gid]; a_h[i][3] = TaH[r4 + m+gid+8];
                a_l[i][0] = TaL[r0 + m+gid]; a_l[i][1] = TaL[r0 + m+gid+8];
                a_l[i][2] = TaL[r4 + m+gid]; a_l[i][3] = TaL[r4 + m+gid+8];
            }
            #pragma unroll
            for (int j = 0; j < 4; j++) {
                int n = wn*32 + j*8;
                unsigned b_h[2] = { Wh[s0 + n+gid], Wh[s4 + n+gid] };
                unsigned b_l[2] = { Wl[s0 + n+gid], Wl[s4 + n+gid] };
                #pragma unroll
                for (int i = 0; i < 3; i++) {
                    mma16(acc[i][j], a_h[i], b_h);
                    mma16(acc[i][j], a_h[i], b_l);
                    mma16(acc[i][j], a_l[i], b_h);
                }
            }
            // no trailing sync (double-buffered W; Ta read-only here)
        }
        __syncthreads();   // Ta reads done before Hb-next overwrites U
        // ---- epilogue: relu(+bias) -> g_xcp; next Hb via shuffles ----
        const float* bias = bs[L];
        #pragma unroll
        for (int i = 0; i < 3; i++) {
            #pragma unroll
            for (int j = 0; j < 4; j++) {
                int m = wm*48 + i*16 + gid;
                int n = wn*32 + j*8 + 2*tig;
                float b0 = bias[n], b1 = bias[n+1];
                float v0 = fmaxf(acc[i][j][0] + b0, 0.0f);
                float v1 = fmaxf(acc[i][j][1] + b1, 0.0f);
                float v2 = fmaxf(acc[i][j][2] + b0, 0.0f);
                float v3 = fmaxf(acc[i][j][3] + b1, 0.0f);
                int p2 = L*64 + (n >> 1);
                if (m < NODES) {
                    unsigned h, l; f2bf2(v0, v1, h, l);
                    g_xcp[((long)g*NODES + m)*XCP + p2] = make_uint2(h, l);
                }
                if (m + 8 < NODES) {
                    unsigned h, l; f2bf2(v2, v3, h, l);
                    g_xcp[((long)g*NODES + m + 8)*XCP + p2] = make_uint2(h, l);
                }
                if (L < 2) {
                    float q0 = __shfl_down_sync(0xffffffffu, v0, 4);
                    float q1 = __shfl_down_sync(0xffffffffu, v1, 4);
                    float q2 = __shfl_down_sync(0xffffffffu, v2, 4);
                    float q3 = __shfl_down_sync(0xffffffffu, v3, 4);
                    if (!(gid & 1)) {   // even gid owns node pair (m, m+1)
                        int k2 = wm*24 + i*8 + (gid >> 1);
                        unsigned h, l;
                        f2bf2(v0, q0, h, l); HbH[k2*NP + n]       = h; HbL[k2*NP + n]       = l;
                        f2bf2(v1, q1, h, l); HbH[k2*NP + n + 1]   = h; HbL[k2*NP + n + 1]   = l;
                        f2bf2(v2, q2, h, l); HbH[(k2+4)*NP + n]   = h; HbL[(k2+4)*NP + n]   = l;
                        f2bf2(v3, q3, h, l); HbH[(k2+4)*NP + n+1] = h; HbL[(k2+4)*NP + n+1] = l;
                    }
                }
            }
        }
    }
}

// ================= lin1: single wave, KC=240 pairs, fully pre-split =================
__global__ void __launch_bounds__(256, 2) k_lin1() {
    __shared__ uint2 As[2][8][SBL];
    __shared__ uint2 Bs[2][8][68];
    const int t = threadIdx.x, lane = t & 31, wid = t >> 5;
    const int wm = wid >> 1, wn = wid & 1;
    const int gid = lane >> 2, tig = lane & 3;
    const int row0   = blockIdx.x * 128;
    const int kbase2 = blockIdx.y * 240;     // pair units
    const int KT = 30;

    const int am  = t >> 1;             // A row (0..127)
    const int ak0 = (t & 1) * 4;        // A pair base within k-tile (0 or 4)
    const int bk0 = t >> 5;             // B k2 row (0..7)
    const int bn0 = (t*2) & 63;         // B col base (even)

    uint4 rA0, rA1, rB;
    auto load_tile = [&](int kt) {
        const uint2* p = &g_xcp[(long)(row0 + am)*LDA1P + kbase2 + kt*8 + ak0];
        rA0 = *(const uint4*)p;
        rA1 = *(const uint4*)(p + 2);
        rB  = *(const uint4*)&g_l1w[(kbase2 + kt*8 + bk0)*64 + bn0];
    };

    float acc[2][4][4];
    #pragma unroll
    for (int i = 0; i < 2; i++)
        #pragma unroll
        for (int j = 0; j < 4; j++)
            #pragma unroll
            for (int q = 0; q < 4; q++) acc[i][j][q] = 0.0f;

    load_tile(0);
    for (int kt = 0; kt < KT; kt++) {
        int buf = kt & 1;
        As[buf][ak0  ][am] = make_uint2(rA0.x, rA0.y);
        As[buf][ak0+1][am] = make_uint2(rA0.z, rA0.w);
        As[buf][ak0+2][am] = make_uint2(rA1.x, rA1.y);
        As[buf][ak0+3][am] = make_uint2(rA1.z, rA1.w);
        *(uint4*)&Bs[buf][bk0][bn0] = rB;
        __syncthreads();
        if (kt + 1 < KT) load_tile(kt + 1);

        uint2 a[2][4];
        #pragma unroll
        for (int i = 0; i < 2; i++) {
            int m = wm*32 + i*16;
            a[i][0] = As[buf][tig  ][m+gid]; a[i][1] = As[buf][tig  ][m+gid+8];
            a[i][2] = As[buf][tig+4][m+gid]; a[i][3] = As[buf][tig+4][m+gid+8];
        }
        #pragma unroll
        for (int j = 0; j < 4; j++) {
            int n = wn*32 + j*8;
            uint2 b[2] = { Bs[buf][tig][n+gid], Bs[buf][tig+4][n+gid] };
            #pragma unroll
            for (int i = 0; i < 2; i++) mma3u(acc[i][j], a[i], b);
        }
    }
    #pragma unroll
    for (int j = 0; j < 4; j++) {
        int n = wn*32 + j*8 + 2*tig;
        #pragma unroll
        for (int i = 0; i < 2; i++) {
            int r = row0 + wm*32 + i*16 + gid;
            atomicAdd(&g_acc[r*HL + n],         acc[i][j][0]);
            atomicAdd(&g_acc[r*HL + n + 1],     acc[i][j][1]);
            atomicAdd(&g_acc[(r+8)*HL + n],     acc[i][j][2]);
            atomicAdd(&g_acc[(r+8)*HL + n + 1], acc[i][j][3]);
        }
    }
}

// ================= epilogue =================
__global__ void k_final(const float* __restrict__ b1, const float* __restrict__ W2,
                        const float* __restrict__ b2, float* __restrict__ out) {
    int g = blockIdx.x*blockDim.x + threadIdx.x;
    if (g >= BG) return;
    float l0 = b2[0], l1 = b2[1];
    #pragma unroll 8
    for (int j = 0; j < HL; j++) {
        float h = fmaxf(g_acc[g*HL + j] + b1[j], 0.0f);
        l0 = fmaf(h, W2[j*2 + 0], l0);
        l1 = fmaf(h, W2[j*2 + 1], l1);
    }
    float m = fmaxf(l0, l1);
    float lse = m + logf(expf(l0 - m) + expf(l1 - m));
    out[g*2 + 0] = l0 - lse;
    out[g*2 + 1] = l1 - lse;
}

// ================= launch =================
extern "C" void kernel_launch(void* const* d_in, const int* in_sizes, int n_in,
                              void* d_out, int out_size) {
    const float* x      = (const float*)d_in[0];
    const float* eattr  = (const float*)d_in[1];
    const float* W1     = (const float*)d_in[2];
    const float* b1     = (const float*)d_in[3];
    const float* W2     = (const float*)d_in[4];
    const float* b2     = (const float*)d_in[5];
    const float* W3     = (const float*)d_in[6];
    const float* b3     = (const float*)d_in[7];
    const float* lin1W  = (const float*)d_in[8];
    const float* lin1b  = (const float*)d_in[9];
    const float* lin2W  = (const float*)d_in[10];
    const float* lin2b  = (const float*)d_in[11];
    const int*   eidx   = (const int*)d_in[12];
    float*       out    = (float*)d_out;

    static int attr_set = 0;
    if (!attr_set) {
        cudaFuncSetAttribute(k_fused, cudaFuncAttributeMaxDynamicSharedMemorySize, SMEMB);
        attr_set = 1;
    }

    const int NPREW = 3*64*128 + 17280*64;
    k_prew<<<(NPREW + 255)/256, 256>>>(W1, W2, W3, lin1W);
    k_fused<<<BG, 256, SMEMB>>>(x, eattr, eidx, b1, b2, b3);
    dim3 g1(BG/128, 72);   // KC = 240 pairs -> 288 CTAs = one wave
    k_lin1<<<g1, 256>>>();
    k_final<<<(BG + 255)/256, 256>>>(lin1b, lin2W, lin2b, out);
}

// round 13
// speedup vs baseline: 2.5697x; 1.0256x over previous
#include <cuda_runtime.h>
#include <cuda_bf16.h>
#include <math.h>

#define NN     46080
#define EE     737280
#define BG     512
#define NODES  90
#define EPG    1440
#define HH     128
#define HL     64
#define XCP    192          // xc pairs per node (384 feats / 2)
#define LDA1P  (NODES*XCP)  // 17280 pairs per graph row

#define MP 104              // m-stride (u32) for A/Ta  (104 % 32 == 8: conflict-free)
#define NP 136              // n-stride (u32) for Hb    (136 % 32 == 8)
#define SBL 132             // uint2 stride in k_lin1 As

// k_fused smem byte offsets
#define OFF_A0  1024
#define SZ_A    (48*MP*4)            // 19968
#define OFF_A1  (OFF_A0 + SZ_A)
#define OFF_U   (OFF_A1 + SZ_A)      // 40960
#define SZ_U    (2*64*MP*4)          // 53248
#define SMEMB   (OFF_U + SZ_U)       // 94208 bytes (~92 KB) -> 2 CTAs/SM

// ---------------- device scratch ----------------
__device__ uint2    g_xcp[NN*XCP];      // split bf16 pairs {hi,lo}
__device__ float    g_acc[BG*HL];       // lin1 split-K accumulator
__device__ unsigned g_wh[3*64*128];     // conv W hi plane [L][k2][n], zero-padded
__device__ unsigned g_wl[3*64*128];     // conv W lo plane
__device__ uint2    g_l1w[17280*64];    // lin1 W pairs [k2][n]

// ---------------- bf16 split helpers ----------------
__device__ __forceinline__ void f2bf2(float v0, float v1, unsigned &h, unsigned &l) {
    __nv_bfloat16 h0 = __float2bfloat16(v0), h1 = __float2bfloat16(v1);
    float r0 = v0 - __bfloat162float(h0);
    float r1 = v1 - __bfloat162float(h1);
    __nv_bfloat16 l0 = __float2bfloat16(r0), l1 = __float2bfloat16(r1);
    h = ((unsigned)__bfloat16_as_ushort(h1) << 16) | (unsigned)__bfloat16_as_ushort(h0);
    l = ((unsigned)__bfloat16_as_ushort(l1) << 16) | (unsigned)__bfloat16_as_ushort(l0);
}
__device__ __forceinline__ void mma16(float* c, const unsigned* a, const unsigned* b) {
    asm volatile("mma.sync.aligned.m16n8k16.row.col.f32.bf16.bf16.f32 "
        "{%0,%1,%2,%3}, {%4,%5,%6,%7}, {%8,%9}, {%0,%1,%2,%3};"
        : "+f"(c[0]), "+f"(c[1]), "+f"(c[2]), "+f"(c[3])
        : "r"(a[0]), "r"(a[1]), "r"(a[2]), "r"(a[3]), "r"(b[0]), "r"(b[1]));
}
__device__ __forceinline__ void mma3u(float* c, const uint2* a, const uint2* b) {
    unsigned ah[4] = {a[0].x, a[1].x, a[2].x, a[3].x};
    unsigned al[4] = {a[0].y, a[1].y, a[2].y, a[3].y};
    unsigned bh[2] = {b[0].x, b[1].x};
    unsigned bl[2] = {b[0].y, b[1].y};
    mma16(c, ah, bh);
    mma16(c, ah, bl);
    mma16(c, al, bh);
}

// ================= weight pre-split =================
__global__ void k_prew(const float* __restrict__ W1, const float* __restrict__ W2,
                       const float* __restrict__ W3, const float* __restrict__ l1w) {
    int i = blockIdx.x*blockDim.x + threadIdx.x;
    if (i < 3*64*128) {
        int L = i >> 13;
        int r = i & 8191;
        int k2 = r >> 7, n = r & 127;
        const float* W = (L == 0) ? W1 : (L == 1) ? W2 : W3;
        int KW = (L == 0) ? 90 : 128;
        int k = 2*k2;
        float v0 = (k     < KW) ? W[k*HH + n]     : 0.0f;
        float v1 = (k + 1 < KW) ? W[(k+1)*HH + n] : 0.0f;
        unsigned h, l; f2bf2(v0, v1, h, l);
        g_wh[i] = h; g_wl[i] = l;
    } else {
        int j = i - 3*64*128;
        if (j < 17280*64) {
            int k2 = j >> 6, n = j & 63;
            unsigned h, l;
            f2bf2(l1w[(2*k2)*HL + n], l1w[(2*k2+1)*HL + n], h, l);
            g_l1w[j] = make_uint2(h, l);
        }
    }
}

// ================= fused per-graph 3-layer GCN =================
__global__ void __launch_bounds__(256, 2) k_fused(
    const float* __restrict__ x, const float* __restrict__ eattr,
    const int* __restrict__ ei,
    const float* __restrict__ b1, const float* __restrict__ b2,
    const float* __restrict__ b3) {
    extern __shared__ char sm[];
    float*    sdeg = (float*)sm;               // 96 @0
    float*    sdis = (float*)(sm + 512);       // 96 @512
    unsigned* Aah  = (unsigned*)(sm + OFF_A0); // [k2=48][m<=96] stride MP
    unsigned* Aal  = (unsigned*)(sm + OFF_A1);
    unsigned* HbH  = (unsigned*)(sm + OFF_U);                  // [k2=48][n=128] stride NP
    unsigned* HbL  = (unsigned*)(sm + OFF_U + 48*NP*4);
    unsigned* TaH  = (unsigned*)(sm + OFF_U);                  // [k2=64][m<=96] stride MP
    unsigned* TaL  = (unsigned*)(sm + OFF_U + 64*MP*4);
    float*    F    = (float*)(sm + OFF_U);                     // [96][MP] fp32 (prologue only)

    const int g = blockIdx.x, t = threadIdx.x, lane = t & 31, wid = t >> 5;
    const int wm = wid >> 2, wn = wid & 3;      // 2 x 4 warps; warp tile 48x32
    const int gid = lane >> 2, tig = lane & 3;
    const int eb = g * EPG;

    if (t < HL) g_acc[g*HL + t] = 0.0f;

    // ---- prologue: dense normalized adjacency in F (aliases U) ----
    for (int i = t; i < 96*MP; i += 256) F[i] = 0.0f;
    if (t < 96) sdeg[t] = 1.0f;
    __syncthreads();
    for (int e = t; e < EPG; e += 256)
        atomicAdd(&sdeg[ei[EE + eb + e] - g*NODES], eattr[eb + e]);
    __syncthreads();
    if (t < 96) sdis[t] = rsqrtf(sdeg[t]);
    __syncthreads();
    for (int e = t; e < EPG; e += 256) {
        int s = ei[eb + e] - g*NODES;
        int d = ei[EE + eb + e] - g*NODES;
        atomicAdd(&F[d*MP + s], sdis[s] * eattr[eb + e] * sdis[d]);
    }
    if (t < NODES) atomicAdd(&F[t*MP + t], sdis[t]*sdis[t]);
    __syncthreads();
    // ---- A pairs [k2=src/2][m=dst] ----
    for (int i = t; i < 48*96; i += 256) {
        int k2 = i / 96, m = i - 96*k2;
        unsigned h, l; f2bf2(F[m*MP + 2*k2], F[m*MP + 2*k2 + 1], h, l);
        Aah[k2*MP + m] = h; Aal[k2*MP + m] = l;
    }
    __syncthreads();   // F fully consumed before Hb0 overwrites U
    // ---- Hb0 = x^T pairs [k2=node/2][n=feat] ----
    for (int i = t; i < 48*128; i += 256) {
        int k2 = i >> 7, n = i & 127;
        int n0 = 2*k2, n1 = n0 + 1;
        float v0 = (n < 90 && n0 < 90) ? x[((long)g*NODES + n0)*90 + n] : 0.0f;
        float v1 = (n < 90 && n1 < 90) ? x[((long)g*NODES + n1)*90 + n] : 0.0f;
        unsigned h, l; f2bf2(v0, v1, h, l);
        HbH[k2*NP + n] = h; HbL[k2*NP + n] = l;
    }

    const float* bs[3]  = {b1, b2, b3};
    const int    KT2s[3] = {6, 8, 8};
    float acc[3][4][4];

    for (int L = 0; L < 3; L++) {
        __syncthreads();   // Hb ready
        // ======== GEMM1: T[m=96][n=128] = A @ Hb, K=96 ========
        #pragma unroll
        for (int i = 0; i < 3; i++)
            #pragma unroll
            for (int j = 0; j < 4; j++)
                #pragma unroll
                for (int q = 0; q < 4; q++) acc[i][j][q] = 0.0f;
        for (int kt = 0; kt < 6; kt++) {
            int r0 = (kt*8 + tig)*MP, r4 = r0 + 4*MP;
            int s0 = (kt*8 + tig)*NP, s4 = s0 + 4*NP;
            unsigned a_h[3][4], a_l[3][4];
            #pragma unroll
            for (int i = 0; i < 3; i++) {
                int m = wm*48 + i*16;
                a_h[i][0] = Aah[r0 + m+gid]; a_h[i][1] = Aah[r0 + m+gid+8];
                a_h[i][2] = Aah[r4 + m+gid]; a_h[i][3] = Aah[r4 + m+gid+8];
                a_l[i][0] = Aal[r0 + m+gid]; a_l[i][1] = Aal[r0 + m+gid+8];
                a_l[i][2] = Aal[r4 + m+gid]; a_l[i][3] = Aal[r4 + m+gid+8];
            }
            #pragma unroll
            for (int j = 0; j < 4; j++) {
                int n = wn*32 + j*8;
                unsigned b_h[2] = { HbH[s0 + n+gid], HbH[s4 + n+gid] };
                unsigned b_l[2] = { HbL[s0 + n+gid], HbL[s4 + n+gid] };
                #pragma unroll
                for (int i = 0; i < 3; i++) {
                    mma16(acc[i][j], a_h[i], b_h);
                    mma16(acc[i][j], a_h[i], b_l);
                    mma16(acc[i][j], a_l[i], b_h);
                }
            }
        }
        __syncthreads();   // all Hb reads done; U reusable
        // ---- T -> Ta pairs [k2=feat/2][m] ----
        #pragma unroll
        for (int j = 0; j < 4; j++) {
            int k2 = wn*16 + j*4 + tig;
            #pragma unroll
            for (int i = 0; i < 3; i++) {
                int m = wm*48 + i*16 + gid;
                unsigned h, l;
                f2bf2(acc[i][j][0], acc[i][j][1], h, l);
                TaH[k2*MP + m] = h; TaL[k2*MP + m] = l;
                f2bf2(acc[i][j][2], acc[i][j][3], h, l);
                TaH[k2*MP + m+8] = h; TaL[k2*MP + m+8] = l;
            }
        }
        __syncthreads();   // Ta ready
        // ======== GEMM2: H = Ta @ W  (W fragments direct from gmem/L2) ========
        #pragma unroll
        for (int i = 0; i < 3; i++)
            #pragma unroll
            for (int j = 0; j < 4; j++)
                #pragma unroll
                for (int q = 0; q < 4; q++) acc[i][j][q] = 0.0f;
        const unsigned* WhP = g_wh + L*8192;
        const unsigned* WlP = g_wl + L*8192;
        const int KT2 = KT2s[L];
        for (int kt = 0; kt < KT2; kt++) {
            // B fragments: LDG (L2-resident, shared across all CTAs)
            unsigned b_h[4][2], b_l[4][2];
            int w0 = (kt*8 + tig)*128, w4 = w0 + 4*128;
            #pragma unroll
            for (int j = 0; j < 4; j++) {
                int n = wn*32 + j*8 + gid;
                b_h[j][0] = WhP[w0 + n]; b_h[j][1] = WhP[w4 + n];
                b_l[j][0] = WlP[w0 + n]; b_l[j][1] = WlP[w4 + n];
            }
            int r0 = (kt*8 + tig)*MP, r4 = r0 + 4*MP;
            unsigned a_h[3][4], a_l[3][4];
            #pragma unroll
            for (int i = 0; i < 3; i++) {
                int m = wm*48 + i*16;
                a_h[i][0] = TaH[r0 + m+gid]; a_h[i][1] = TaH[r0 + m+gid+8];
                a_h[i][2] = TaH[r4 + m+gid]; a_h[i][3] = TaH[r4 + m+gid+8];
                a_l[i][0] = TaL[r0 + m+gid]; a_l[i][1] = TaL[r0 + m+gid+8];
                a_l[i][2] = TaL[r4 + m+gid]; a_l[i][3] = TaL[r4 + m+gid+8];
            }
            #pragma unroll
            for (int j = 0; j < 4; j++) {
                #pragma unroll
                for (int i = 0; i < 3; i++) {
                    mma16(acc[i][j], a_h[i], b_h[j]);
                    mma16(acc[i][j], a_h[i], b_l[j]);
                    mma16(acc[i][j], a_l[i], b_h[j]);
                }
            }
        }
        __syncthreads();   // Ta reads done before Hb-next overwrites U
        // ---- epilogue: relu(+bias) -> g_xcp; next Hb via shuffles ----
        const float* bias = bs[L];
        #pragma unroll
        for (int i = 0; i < 3; i++) {
            #pragma unroll
            for (int j = 0; j < 4; j++) {
                int m = wm*48 + i*16 + gid;
                int n = wn*32 + j*8 + 2*tig;
                float b0 = bias[n], b1 = bias[n+1];
                float v0 = fmaxf(acc[i][j][0] + b0, 0.0f);
                float v1 = fmaxf(acc[i][j][1] + b1, 0.0f);
                float v2 = fmaxf(acc[i][j][2] + b0, 0.0f);
                float v3 = fmaxf(acc[i][j][3] + b1, 0.0f);
                int p2 = L*64 + (n >> 1);
                if (m < NODES) {
                    unsigned h, l; f2bf2(v0, v1, h, l);
                    g_xcp[((long)g*NODES + m)*XCP + p2] = make_uint2(h, l);
                }
                if (m + 8 < NODES) {
                    unsigned h, l; f2bf2(v2, v3, h, l);
                    g_xcp[((long)g*NODES + m + 8)*XCP + p2] = make_uint2(h, l);
                }
                if (L < 2) {
                    float q0 = __shfl_down_sync(0xffffffffu, v0, 4);
                    float q1 = __shfl_down_sync(0xffffffffu, v1, 4);
                    float q2 = __shfl_down_sync(0xffffffffu, v2, 4);
                    float q3 = __shfl_down_sync(0xffffffffu, v3, 4);
                    if (!(gid & 1)) {   // even gid owns node pair (m, m+1)
                        int k2 = wm*24 + i*8 + (gid >> 1);
                        unsigned h, l;
                        f2bf2(v0, q0, h, l); HbH[k2*NP + n]       = h; HbL[k2*NP + n]       = l;
                        f2bf2(v1, q1, h, l); HbH[k2*NP + n + 1]   = h; HbL[k2*NP + n + 1]   = l;
                        f2bf2(v2, q2, h, l); HbH[(k2+4)*NP + n]   = h; HbL[(k2+4)*NP + n]   = l;
                        f2bf2(v3, q3, h, l); HbH[(k2+4)*NP + n+1] = h; HbL[(k2+4)*NP + n+1] = l;
                    }
                }
            }
        }
    }
}

// ================= lin1: single wave, KC=240 pairs, fully pre-split =================
__global__ void __launch_bounds__(256, 2) k_lin1() {
    __shared__ uint2 As[2][8][SBL];
    __shared__ uint2 Bs[2][8][68];
    const int t = threadIdx.x, lane = t & 31, wid = t >> 5;
    const int wm = wid >> 1, wn = wid & 1;
    const int gid = lane >> 2, tig = lane & 3;
    const int row0   = blockIdx.x * 128;
    const int kbase2 = blockIdx.y * 240;     // pair units
    const int KT = 30;

    const int am  = t >> 1;
    const int ak0 = (t & 1) * 4;
    const int bk0 = t >> 5;
    const int bn0 = (t*2) & 63;

    uint4 rA0, rA1, rB;
    auto load_tile = [&](int kt) {
        const uint2* p = &g_xcp[(long)(row0 + am)*LDA1P + kbase2 + kt*8 + ak0];
        rA0 = *(const uint4*)p;
        rA1 = *(const uint4*)(p + 2);
        rB  = *(const uint4*)&g_l1w[(kbase2 + kt*8 + bk0)*64 + bn0];
    };

    float acc[2][4][4];
    #pragma unroll
    for (int i = 0; i < 2; i++)
        #pragma unroll
        for (int j = 0; j < 4; j++)
            #pragma unroll
            for (int q = 0; q < 4; q++) acc[i][j][q] = 0.0f;

    load_tile(0);
    for (int kt = 0; kt < KT; kt++) {
        int buf = kt & 1;
        As[buf][ak0  ][am] = make_uint2(rA0.x, rA0.y);
        As[buf][ak0+1][am] = make_uint2(rA0.z, rA0.w);
        As[buf][ak0+2][am] = make_uint2(rA1.x, rA1.y);
        As[buf][ak0+3][am] = make_uint2(rA1.z, rA1.w);
        *(uint4*)&Bs[buf][bk0][bn0] = rB;
        __syncthreads();
        if (kt + 1 < KT) load_tile(kt + 1);

        uint2 a[2][4];
        #pragma unroll
        for (int i = 0; i < 2; i++) {
            int m = wm*32 + i*16;
            a[i][0] = As[buf][tig  ][m+gid]; a[i][1] = As[buf][tig  ][m+gid+8];
            a[i][2] = As[buf][tig+4][m+gid]; a[i][3] = As[buf][tig+4][m+gid+8];
        }
        #pragma unroll
        for (int j = 0; j < 4; j++) {
            int n = wn*32 + j*8;
            uint2 b[2] = { Bs[buf][tig][n+gid], Bs[buf][tig+4][n+gid] };
            #pragma unroll
            for (int i = 0; i < 2; i++) mma3u(acc[i][j], a[i], b);
        }
    }
    #pragma unroll
    for (int j = 0; j < 4; j++) {
        int n = wn*32 + j*8 + 2*tig;
        #pragma unroll
        for (int i = 0; i < 2; i++) {
            int r = row0 + wm*32 + i*16 + gid;
            atomicAdd(&g_acc[r*HL + n],         acc[i][j][0]);
            atomicAdd(&g_acc[r*HL + n + 1],     acc[i][j][1]);
            atomicAdd(&g_acc[(r+8)*HL + n],     acc[i][j][2]);
            atomicAdd(&g_acc[(r+8)*HL + n + 1], acc[i][j][3]);
        }
    }
}

// ================= epilogue: warp per graph =================
__global__ void k_final(const float* __restrict__ b1, const float* __restrict__ W2,
                        const float* __restrict__ b2, float* __restrict__ out) {
    int w = (blockIdx.x*blockDim.x + threadIdx.x) >> 5;   // graph id
    int lane = threadIdx.x & 31;
    if (w >= BG) return;
    float h0 = fmaxf(g_acc[w*HL + lane]      + b1[lane],      0.0f);
    float h1 = fmaxf(g_acc[w*HL + lane + 32] + b1[lane + 32], 0.0f);
    float l0 = h0*W2[lane*2]     + h1*W2[(lane+32)*2];
    float l1 = h0*W2[lane*2 + 1] + h1*W2[(lane+32)*2 + 1];
    #pragma unroll
    for (int o = 16; o > 0; o >>= 1) {
        l0 += __shfl_xor_sync(0xffffffffu, l0, o);
        l1 += __shfl_xor_sync(0xffffffffu, l1, o);
    }
    if (lane == 0) {
        l0 += b2[0]; l1 += b2[1];
        float m = fmaxf(l0, l1);
        float lse = m + logf(expf(l0 - m) + expf(l1 - m));
        out[w*2 + 0] = l0 - lse;
        out[w*2 + 1] = l1 - lse;
    }
}

// ================= launch =================
extern "C" void kernel_launch(void* const* d_in, const int* in_sizes, int n_in,
                              void* d_out, int out_size) {
    const float* x      = (const float*)d_in[0];
    const float* eattr  = (const float*)d_in[1];
    const float* W1     = (const float*)d_in[2];
    const float* b1     = (const float*)d_in[3];
    const float* W2     = (const float*)d_in[4];
    const float* b2     = (const float*)d_in[5];
    const float* W3     = (const float*)d_in[6];
    const float* b3     = (const float*)d_in[7];
    const float* lin1W  = (const float*)d_in[8];
    const float* lin1b  = (const float*)d_in[9];
    const float* lin2W  = (const float*)d_in[10];
    const float* lin2b  = (const float*)d_in[11];
    const int*   eidx   = (const int*)d_in[12];
    float*       out    = (float*)d_out;

    static int attr_set = 0;
    if (!attr_set) {
        cudaFuncSetAttribute(k_fused, cudaFuncAttributeMaxDynamicSharedMemorySize, SMEMB);
        attr_set = 1;
    }

    const int NPREW = 3*64*128 + 17280*64;
    k_prew<<<(NPREW + 255)/256, 256>>>(W1, W2, W3, lin1W);
    k_fused<<<BG, 256, SMEMB>>>(x, eattr, eidx, b1, b2, b3);
    dim3 g1(BG/128, 72);   // KC = 240 pairs -> 288 CTAs = one wave
    k_lin1<<<g1, 256>>>();
    k_final<<<BG/8, 256>>>(lin1b, lin2W, lin2b, out);
}

// round 14
// speedup vs baseline: 2.5736x; 1.0015x over previous
#include <cuda_runtime.h>
#include <cuda_bf16.h>
#include <math.h>

#define NN     46080
#define EE     737280
#define BG     512
#define NODES  90
#define EPG    1440
#define HH     128
#define HL     64
#define XCP    192          // xc pairs per node (384 feats / 2)
#define LDA1P  (NODES*XCP)  // 17280 pairs per graph row

#define MPF 104             // fp32 stride for F scratch
#define NP  136             // u32 stride for Hb [k2][n]
#define SBL 132             // uint2 stride in k_lin1 As

// A  : row-major bf16 [m<96][k<96],  row stride 104 halfwords (208B: conflict-free LDSM)
// Ta : row-major bf16 [m<96][k<128], row stride 136 halfwords (272B: conflict-free LDSM)
#define OFF_A0  1024
#define SZ_A    (96*104*2)           // 19968 per plane
#define OFF_A1  (OFF_A0 + SZ_A)
#define OFF_U   (OFF_A1 + SZ_A)      // 40960
#define SZ_TA   (96*136*2)           // 26112 per plane
#define SZ_U    (2*SZ_TA)            // 52224 (Ta 2 planes; Hb 2x26112; F 39936)
#define SMEMB   (OFF_U + SZ_U + 64)  // 93248 bytes -> 2 CTAs/SM

// ---------------- device scratch ----------------
__device__ uint2    g_xcp[NN*XCP];      // split bf16 pairs {hi,lo}
__device__ float    g_acc[BG*HL];       // lin1 split-K accumulator
__device__ unsigned g_wh[3*64*128];     // conv W hi plane [L][k2][n], zero-padded
__device__ unsigned g_wl[3*64*128];     // conv W lo plane
__device__ uint2    g_l1w[17280*64];    // lin1 W pairs [k2][n]

// ---------------- helpers ----------------
__device__ __forceinline__ void f2bf2(float v0, float v1, unsigned &h, unsigned &l) {
    __nv_bfloat16 h0 = __float2bfloat16(v0), h1 = __float2bfloat16(v1);
    float r0 = v0 - __bfloat162float(h0);
    float r1 = v1 - __bfloat162float(h1);
    __nv_bfloat16 l0 = __float2bfloat16(r0), l1 = __float2bfloat16(r1);
    h = ((unsigned)__bfloat16_as_ushort(h1) << 16) | (unsigned)__bfloat16_as_ushort(h0);
    l = ((unsigned)__bfloat16_as_ushort(l1) << 16) | (unsigned)__bfloat16_as_ushort(l0);
}
__device__ __forceinline__ void mma16(float* c, const unsigned* a, const unsigned* b) {
    asm volatile("mma.sync.aligned.m16n8k16.row.col.f32.bf16.bf16.f32 "
        "{%0,%1,%2,%3}, {%4,%5,%6,%7}, {%8,%9}, {%0,%1,%2,%3};"
        : "+f"(c[0]), "+f"(c[1]), "+f"(c[2]), "+f"(c[3])
        : "r"(a[0]), "r"(a[1]), "r"(a[2]), "r"(a[3]), "r"(b[0]), "r"(b[1]));
}
__device__ __forceinline__ void mma3u(float* c, const uint2* a, const uint2* b) {
    unsigned ah[4] = {a[0].x, a[1].x, a[2].x, a[3].x};
    unsigned al[4] = {a[0].y, a[1].y, a[2].y, a[3].y};
    unsigned bh[2] = {b[0].x, b[1].x};
    unsigned bl[2] = {b[0].y, b[1].y};
    mma16(c, ah, bh);
    mma16(c, ah, bl);
    mma16(c, al, bh);
}
__device__ __forceinline__ void ldsm4(unsigned* r, unsigned addr) {
    asm volatile("ldmatrix.sync.aligned.m8n8.x4.shared.b16 {%0,%1,%2,%3}, [%4];"
        : "=r"(r[0]), "=r"(r[1]), "=r"(r[2]), "=r"(r[3]) : "r"(addr));
}

// ================= weight pre-split =================
__global__ void k_prew(const float* __restrict__ W1, const float* __restrict__ W2,
                       const float* __restrict__ W3, const float* __restrict__ l1w) {
    int i = blockIdx.x*blockDim.x + threadIdx.x;
    if (i < 3*64*128) {
        int L = i >> 13;
        int r = i & 8191;
        int k2 = r >> 7, n = r & 127;
        const float* W = (L == 0) ? W1 : (L == 1) ? W2 : W3;
        int KW = (L == 0) ? 90 : 128;
        int k = 2*k2;
        float v0 = (k     < KW) ? W[k*HH + n]     : 0.0f;
        float v1 = (k + 1 < KW) ? W[(k+1)*HH + n] : 0.0f;
        unsigned h, l; f2bf2(v0, v1, h, l);
        g_wh[i] = h; g_wl[i] = l;
    } else {
        int j = i - 3*64*128;
        if (j < 17280*64) {
            int k2 = j >> 6, n = j & 63;
            unsigned h, l;
            f2bf2(l1w[(2*k2)*HL + n], l1w[(2*k2+1)*HL + n], h, l);
            g_l1w[j] = make_uint2(h, l);
        }
    }
}

// ================= fused per-graph 3-layer GCN (ldmatrix A-path) =================
__global__ void __launch_bounds__(256, 2) k_fused(
    const float* __restrict__ x, const float* __restrict__ eattr,
    const int* __restrict__ ei,
    const float* __restrict__ b1, const float* __restrict__ b2,
    const float* __restrict__ b3) {
    extern __shared__ char sm[];
    float*    sdeg = (float*)sm;               // 96 @0
    float*    sdis = (float*)(sm + 512);       // 96 @512
    unsigned* AaWH = (unsigned*)(sm + OFF_A0); // A hi: row-major word [m][k2<48], 52 w/row
    unsigned* AaWL = (unsigned*)(sm + OFF_A1);
    unsigned* HbH  = (unsigned*)(sm + OFF_U);                 // [k2=48][n=128] stride NP
    unsigned* HbL  = (unsigned*)(sm + OFF_U + 26112);
    unsigned* TaWH = (unsigned*)(sm + OFF_U);                 // Ta hi: word [m][k2<64], 68 w/row
    unsigned* TaWL = (unsigned*)(sm + OFF_U + SZ_TA);
    float*    F    = (float*)(sm + OFF_U);                    // [96][MPF] fp32 (prologue only)

    const int g = blockIdx.x, t = threadIdx.x, lane = t & 31, wid = t >> 5;
    const int wm = wid >> 2, wn = wid & 3;      // 2 x 4 warps; warp tile 48x32
    const int gid = lane >> 2, tig = lane & 3;
    const int eb = g * EPG;

    // LDSM per-lane byte offsets (row = lane&15, col-block = (lane>>4)*8)
    const unsigned aBaseH  = (unsigned)__cvta_generic_to_shared(sm + OFF_A0);
    const unsigned aBaseL  = (unsigned)__cvta_generic_to_shared(sm + OFF_A1);
    const unsigned taBaseH = (unsigned)__cvta_generic_to_shared(sm + OFF_U);
    const unsigned taBaseL = taBaseH + SZ_TA;
    const int rk104 = ((lane & 15)*104 + (lane >> 4)*8) * 2;
    const int rk136 = ((lane & 15)*136 + (lane >> 4)*8) * 2;

    if (t < HL) g_acc[g*HL + t] = 0.0f;

    // ---- prologue: dense normalized adjacency in F (aliases U) ----
    for (int i = t; i < 96*MPF; i += 256) F[i] = 0.0f;
    if (t < 96) sdeg[t] = 1.0f;
    __syncthreads();
    for (int e = t; e < EPG; e += 256)
        atomicAdd(&sdeg[ei[EE + eb + e] - g*NODES], eattr[eb + e]);
    __syncthreads();
    if (t < 96) sdis[t] = rsqrtf(sdeg[t]);
    __syncthreads();
    for (int e = t; e < EPG; e += 256) {
        int s = ei[eb + e] - g*NODES;
        int d = ei[EE + eb + e] - g*NODES;
        atomicAdd(&F[d*MPF + s], sdis[s] * eattr[eb + e] * sdis[d]);
    }
    if (t < NODES) atomicAdd(&F[t*MPF + t], sdis[t]*sdis[t]);
    __syncthreads();
    // ---- A row-major pairs: word [m][k2] (rows/cols >=90 already zero in F) ----
    for (int i = t; i < 96*48; i += 256) {
        int m = i / 48, k2 = i - 48*m;
        unsigned h, l; f2bf2(F[m*MPF + 2*k2], F[m*MPF + 2*k2 + 1], h, l);
        AaWH[m*52 + k2] = h; AaWL[m*52 + k2] = l;
    }
    __syncthreads();   // F fully consumed before Hb0 overwrites U
    // ---- Hb0 = x^T pairs [k2=node/2][n=feat] ----
    for (int i = t; i < 48*128; i += 256) {
        int k2 = i >> 7, n = i & 127;
        int n0 = 2*k2, n1 = n0 + 1;
        float v0 = (n < 90 && n0 < 90) ? x[((long)g*NODES + n0)*90 + n] : 0.0f;
        float v1 = (n < 90 && n1 < 90) ? x[((long)g*NODES + n1)*90 + n] : 0.0f;
        unsigned h, l; f2bf2(v0, v1, h, l);
        HbH[k2*NP + n] = h; HbL[k2*NP + n] = l;
    }

    const float* bs[3]  = {b1, b2, b3};
    const int    KT2s[3] = {6, 8, 8};
    float acc[3][4][4];

    for (int L = 0; L < 3; L++) {
        __syncthreads();   // Hb ready
        // ======== GEMM1: T[m=96][n=128] = A @ Hb, K=96 (A via LDSM) ========
        #pragma unroll
        for (int i = 0; i < 3; i++)
            #pragma unroll
            for (int j = 0; j < 4; j++)
                #pragma unroll
                for (int q = 0; q < 4; q++) acc[i][j][q] = 0.0f;
        for (int kt = 0; kt < 6; kt++) {
            unsigned a_h[3][4], a_l[3][4];
            #pragma unroll
            for (int i = 0; i < 3; i++) {
                int mo = (wm*48 + i*16)*208 + kt*32;
                ldsm4(a_h[i], aBaseH + mo + rk104);
                ldsm4(a_l[i], aBaseL + mo + rk104);
            }
            int s0 = (kt*8 + tig)*NP, s4 = s0 + 4*NP;
            #pragma unroll
            for (int j = 0; j < 4; j++) {
                int n = wn*32 + j*8;
                unsigned b_h[2] = { HbH[s0 + n+gid], HbH[s4 + n+gid] };
                unsigned b_l[2] = { HbL[s0 + n+gid], HbL[s4 + n+gid] };
                #pragma unroll
                for (int i = 0; i < 3; i++) {
                    mma16(acc[i][j], a_h[i], b_h);
                    mma16(acc[i][j], a_h[i], b_l);
                    mma16(acc[i][j], a_l[i], b_h);
                }
            }
        }
        __syncthreads();   // all Hb reads done; U reusable
        // ---- T -> Ta row-major pairs: word [m][k2=feat/2] ----
        #pragma unroll
        for (int j = 0; j < 4; j++) {
            int n2 = wn*16 + j*4 + tig;
            #pragma unroll
            for (int i = 0; i < 3; i++) {
                int m = wm*48 + i*16 + gid;
                unsigned h, l;
                f2bf2(acc[i][j][0], acc[i][j][1], h, l);
                TaWH[m*68 + n2] = h; TaWL[m*68 + n2] = l;
                f2bf2(acc[i][j][2], acc[i][j][3], h, l);
                TaWH[(m+8)*68 + n2] = h; TaWL[(m+8)*68 + n2] = l;
            }
        }
        __syncthreads();   // Ta ready
        // ======== GEMM2: H = Ta @ W  (Ta via LDSM; W direct from gmem/L2) ========
        #pragma unroll
        for (int i = 0; i < 3; i++)
            #pragma unroll
            for (int j = 0; j < 4; j++)
                #pragma unroll
                for (int q = 0; q < 4; q++) acc[i][j][q] = 0.0f;
        const unsigned* WhP = g_wh + L*8192;
        const unsigned* WlP = g_wl + L*8192;
        const int KT2 = KT2s[L];
        for (int kt = 0; kt < KT2; kt++) {
            unsigned b_h[4][2], b_l[4][2];
            int w0 = (kt*8 + tig)*128, w4 = w0 + 4*128;
            #pragma unroll
            for (int j = 0; j < 4; j++) {
                int n = wn*32 + j*8 + gid;
                b_h[j][0] = WhP[w0 + n]; b_h[j][1] = WhP[w4 + n];
                b_l[j][0] = WlP[w0 + n]; b_l[j][1] = WlP[w4 + n];
            }
            unsigned a_h[3][4], a_l[3][4];
            #pragma unroll
            for (int i = 0; i < 3; i++) {
                int mo = (wm*48 + i*16)*272 + kt*32;
                ldsm4(a_h[i], taBaseH + mo + rk136);
                ldsm4(a_l[i], taBaseL + mo + rk136);
            }
            #pragma unroll
            for (int j = 0; j < 4; j++) {
                #pragma unroll
                for (int i = 0; i < 3; i++) {
                    mma16(acc[i][j], a_h[i], b_h[j]);
                    mma16(acc[i][j], a_h[i], b_l[j]);
                    mma16(acc[i][j], a_l[i], b_h[j]);
                }
            }
        }
        __syncthreads();   // Ta reads done before Hb-next overwrites U
        // ---- epilogue: relu(+bias) -> g_xcp; next Hb via shuffles ----
        const float* bias = bs[L];
        #pragma unroll
        for (int i = 0; i < 3; i++) {
            #pragma unroll
            for (int j = 0; j < 4; j++) {
                int m = wm*48 + i*16 + gid;
                int n = wn*32 + j*8 + 2*tig;
                float b0 = bias[n], b1 = bias[n+1];
                float v0 = fmaxf(acc[i][j][0] + b0, 0.0f);
                float v1 = fmaxf(acc[i][j][1] + b1, 0.0f);
                float v2 = fmaxf(acc[i][j][2] + b0, 0.0f);
                float v3 = fmaxf(acc[i][j][3] + b1, 0.0f);
                int p2 = L*64 + (n >> 1);
                if (m < NODES) {
                    unsigned h, l; f2bf2(v0, v1, h, l);
                    g_xcp[((long)g*NODES + m)*XCP + p2] = make_uint2(h, l);
                }
                if (m + 8 < NODES) {
                    unsigned h, l; f2bf2(v2, v3, h, l);
                    g_xcp[((long)g*NODES + m + 8)*XCP + p2] = make_uint2(h, l);
                }
                if (L < 2) {
                    float q0 = __shfl_down_sync(0xffffffffu, v0, 4);
                    float q1 = __shfl_down_sync(0xffffffffu, v1, 4);
                    float q2 = __shfl_down_sync(0xffffffffu, v2, 4);
                    float q3 = __shfl_down_sync(0xffffffffu, v3, 4);
                    if (!(gid & 1)) {   // even gid owns node pair (m, m+1)
                        int k2 = wm*24 + i*8 + (gid >> 1);
                        unsigned h, l;
                        f2bf2(v0, q0, h, l); HbH[k2*NP + n]       = h; HbL[k2*NP + n]       = l;
                        f2bf2(v1, q1, h, l); HbH[k2*NP + n + 1]   = h; HbL[k2*NP + n + 1]   = l;
                        f2bf2(v2, q2, h, l); HbH[(k2+4)*NP + n]   = h; HbL[(k2+4)*NP + n]   = l;
                        f2bf2(v3, q3, h, l); HbH[(k2+4)*NP + n+1] = h; HbL[(k2+4)*NP + n+1] = l;
                    }
                }
            }
        }
    }
}

// ================= lin1: single wave, KC=240 pairs, fully pre-split =================
__global__ void __launch_bounds__(256, 2) k_lin1() {
    __shared__ uint2 As[2][8][SBL];
    __shared__ uint2 Bs[2][8][68];
    const int t = threadIdx.x, lane = t & 31, wid = t >> 5;
    const int wm = wid >> 1, wn = wid & 1;
    const int gid = lane >> 2, tig = lane & 3;
    const int row0   = blockIdx.x * 128;
    const int kbase2 = blockIdx.y * 240;     // pair units
    const int KT = 30;

    const int am  = t >> 1;
    const int ak0 = (t & 1) * 4;
    const int bk0 = t >> 5;
    const int bn0 = (t*2) & 63;

    uint4 rA0, rA1, rB;
    auto load_tile = [&](int kt) {
        const uint2* p = &g_xcp[(long)(row0 + am)*LDA1P + kbase2 + kt*8 + ak0];
        rA0 = *(const uint4*)p;
        rA1 = *(const uint4*)(p + 2);
        rB  = *(const uint4*)&g_l1w[(kbase2 + kt*8 + bk0)*64 + bn0];
    };

    float acc[2][4][4];
    #pragma unroll
    for (int i = 0; i < 2; i++)
        #pragma unroll
        for (int j = 0; j < 4; j++)
            #pragma unroll
            for (int q = 0; q < 4; q++) acc[i][j][q] = 0.0f;

    load_tile(0);
    for (int kt = 0; kt < KT; kt++) {
        int buf = kt & 1;
        As[buf][ak0  ][am] = make_uint2(rA0.x, rA0.y);
        As[buf][ak0+1][am] = make_uint2(rA0.z, rA0.w);
        As[buf][ak0+2][am] = make_uint2(rA1.x, rA1.y);
        As[buf][ak0+3][am] = make_uint2(rA1.z, rA1.w);
        *(uint4*)&Bs[buf][bk0][bn0] = rB;
        __syncthreads();
        if (kt + 1 < KT) load_tile(kt + 1);

        uint2 a[2][4];
        #pragma unroll
        for (int i = 0; i < 2; i++) {
            int m = wm*32 + i*16;
            a[i][0] = As[buf][tig  ][m+gid]; a[i][1] = As[buf][tig  ][m+gid+8];
            a[i][2] = As[buf][tig+4][m+gid]; a[i][3] = As[buf][tig+4][m+gid+8];
        }
        #pragma unroll
        for (int j = 0; j < 4; j++) {
            int n = wn*32 + j*8;
            uint2 b[2] = { Bs[buf][tig][n+gid], Bs[buf][tig+4][n+gid] };
            #pragma unroll
            for (int i = 0; i < 2; i++) mma3u(acc[i][j], a[i], b);
        }
    }
    #pragma unroll
    for (int j = 0; j < 4; j++) {
        int n = wn*32 + j*8 + 2*tig;
        #pragma unroll
        for (int i = 0; i < 2; i++) {
            int r = row0 + wm*32 + i*16 + gid;
            atomicAdd(&g_acc[r*HL + n],         acc[i][j][0]);
            atomicAdd(&g_acc[r*HL + n + 1],     acc[i][j][1]);
            atomicAdd(&g_acc[(r+8)*HL + n],     acc[i][j][2]);
            atomicAdd(&g_acc[(r+8)*HL + n + 1], acc[i][j][3]);
        }
    }
}

// ================= epilogue: warp per graph =================
__global__ void k_final(const float* __restrict__ b1, const float* __restrict__ W2,
                        const float* __restrict__ b2, float* __restrict__ out) {
    int w = (blockIdx.x*blockDim.x + threadIdx.x) >> 5;   // graph id
    int lane = threadIdx.x & 31;
    if (w >= BG) return;
    float h0 = fmaxf(g_acc[w*HL + lane]      + b1[lane],      0.0f);
    float h1 = fmaxf(g_acc[w*HL + lane + 32] + b1[lane + 32], 0.0f);
    float l0 = h0*W2[lane*2]     + h1*W2[(lane+32)*2];
    float l1 = h0*W2[lane*2 + 1] + h1*W2[(lane+32)*2 + 1];
    #pragma unroll
    for (int o = 16; o > 0; o >>= 1) {
        l0 += __shfl_xor_sync(0xffffffffu, l0, o);
        l1 += __shfl_xor_sync(0xffffffffu, l1, o);
    }
    if (lane == 0) {
        l0 += b2[0]; l1 += b2[1];
        float m = fmaxf(l0, l1);
        float lse = m + logf(expf(l0 - m) + expf(l1 - m));
        out[w*2 + 0] = l0 - lse;
        out[w*2 + 1] = l1 - lse;
    }
}

// ================= launch =================
extern "C" void kernel_launch(void* const* d_in, const int* in_sizes, int n_in,
                              void* d_out, int out_size) {
    const float* x      = (const float*)d_in[0];
    const float* eattr  = (const float*)d_in[1];
    const float* W1     = (const float*)d_in[2];
    const float* b1     = (const float*)d_in[3];
    const float* W2     = (const float*)d_in[4];
    const float* b2     = (const float*)d_in[5];
    const float* W3     = (const float*)d_in[6];
    const float* b3     = (const float*)d_in[7];
    const float* lin1W  = (const float*)d_in[8];
    const float* lin1b  = (const float*)d_in[9];
    const float* lin2W  = (const float*)d_in[10];
    const float* lin2b  = (const float*)d_in[11];
    const int*   eidx   = (const int*)d_in[12];
    float*       out    = (float*)d_out;

    static int attr_set = 0;
    if (!attr_set) {
        cudaFuncSetAttribute(k_fused, cudaFuncAttributeMaxDynamicSharedMemorySize, SMEMB);
        attr_set = 1;
    }

    const int NPREW = 3*64*128 + 17280*64;
    k_prew<<<(NPREW + 255)/256, 256>>>(W1, W2, W3, lin1W);
    k_fused<<<BG, 256, SMEMB>>>(x, eattr, eidx, b1, b2, b3);
    dim3 g1(BG/128, 72);   // KC = 240 pairs -> 288 CTAs = one wave
    k_lin1<<<g1, 256>>>();
    k_final<<<BG/8, 256>>>(lin1b, lin2W, lin2b, out);
}